// round 13
// baseline (speedup 1.0000x reference)
#include <cuda_runtime.h>
#include <cuda_bf16.h>
#include <math.h>
#include <stdint.h>

// ---------------------------------------------------------------------------
// LaCT SWIGLU fast-weight attention — mma.sync bf16-split-3 GEMM engine v3.3.
// v3.2 + templated half-N (128x64) CTA tiles for the wave-quantization-heavy
// launches (activation GEMM, NS X' GEMM): finer CTA granularity halves the
// dead time in tail waves of dependent launches.
// ---------------------------------------------------------------------------

#define BH 8
#define TT 4096
#define DD 512
#define DI 512
#define CS 256
#define NCHUNK 15
#define NMAT 24
#define MSZ (512 * 512)
#define AST 40
#define PLANE_H (128 * AST)
#define STAGE_H (4 * PLANE_H)
#define NSTAGE 2
#define SMEM_TOTAL (NSTAGE * STAGE_H * 2)  // 81920 bytes

static constexpr long NM_  = (long)NMAT * MSZ;
static constexpr long W1M_ = 8L * MSZ;
static constexpr long CHB  = (long)CS * DD;
static constexpr long CHT  = (long)BH * CHB;
static constexpr long TDSl = (long)TT * DD;

// fp32 heap
static constexpr long F_WM = 0, F_WC = NM_, F_DM = 2 * NM_;
static constexpr long F_GBA = 3 * NM_, F_HBM = F_GBA + CHT, F_HH = F_HBM + CHT,
                      F_G0 = F_HH + CHT, F_DHID = F_G0 + CHT;
static constexpr long F_WNORM = F_DHID + CHT, F_MI = F_WNORM + NMAT * 512L,
                      F_MLI = F_MI + 8, F_RNS = F_MLI + 8,
                      F_RSP = F_RNS + NMAT, F_TOT = F_RSP + 512;
__device__ __align__(256) float g_f[F_TOT];

// bf16 heap
static constexpr long H_WCH = 0, H_WCL = NM_,
                      H_W1TH = 2 * NM_, H_W1TL = H_W1TH + W1M_,
                      H_XH = H_W1TL + W1M_, H_XL = H_XH + NM_,
                      H_X2H = H_XL + NM_, H_X2L = H_X2H + NM_,
                      H_XTH = H_X2L + NM_, H_XTL = H_XTH + NM_,
                      H_XT2H = H_XTL + NM_, H_XT2L = H_XT2H + NM_,
                      H_AH = H_XT2L + NM_, H_AL = H_AH + NM_,
                      H_BH = H_AL + NM_, H_BL = H_BH + NM_;
static constexpr long H_KH = H_BL + NM_, H_KL = H_KH + CHT, H_QH = H_KL + CHT,
                      H_QL = H_QH + CHT, H_VH = H_QL + CHT, H_VL = H_VH + CHT,
                      H_VTH = H_VL + CHT, H_VTL = H_VTH + CHT,
                      H_K0H = H_VTL + CHT, H_K0L = H_K0H + CHT,
                      H_K2H = H_K0L + CHT, H_K2L = H_K2H + CHT,
                      H_GTH = H_K2L + CHT, H_GTL = H_GTH + CHT,
                      H_HLH = H_GTL + CHT, H_HLL = H_HLH + CHT,
                      H_DGH = H_HLL + CHT, H_DGL = H_DGH + CHT,
                      H_DBH = H_DGL + CHT, H_DBL = H_DBH + CHT,
                      H_TOT = H_DBL + CHT;
__device__ __align__(256) __nv_bfloat16 g_h[H_TOT];

typedef __nv_bfloat16 bf;

// ------------------------- helpers -----------------------------------------
__device__ __forceinline__ uint32_t smem_u32(const void* p) {
    uint32_t a;
    asm("{ .reg .u64 t; cvta.to.shared.u64 t, %1; cvt.u32.u64 %0, t; }" : "=r"(a) : "l"(p));
    return a;
}
__device__ __forceinline__ void cp16(uint32_t dst, const void* src) {
    asm volatile("cp.async.cg.shared.global [%0], [%1], 16;" :: "r"(dst), "l"(src));
}
__device__ __forceinline__ void cp_commit() {
    asm volatile("cp.async.commit_group;" ::: "memory");
}
template <int N>
__device__ __forceinline__ void cp_wait() {
    asm volatile("cp.async.wait_group %0;" :: "n"(N) : "memory");
}
__device__ __forceinline__ void ldm4(uint32_t* f, uint32_t addr) {
    asm volatile("ldmatrix.sync.aligned.m8n8.x4.shared.b16 {%0,%1,%2,%3}, [%4];"
                 : "=r"(f[0]), "=r"(f[1]), "=r"(f[2]), "=r"(f[3]) : "r"(addr));
}
__device__ __forceinline__ void mma16816(float* c, const uint32_t* a, const uint32_t* b) {
    asm volatile("mma.sync.aligned.m16n8k16.row.col.f32.bf16.bf16.f32 "
                 "{%0,%1,%2,%3}, {%4,%5,%6,%7}, {%8,%9}, {%0,%1,%2,%3};"
                 : "+f"(c[0]), "+f"(c[1]), "+f"(c[2]), "+f"(c[3])
                 : "r"(a[0]), "r"(a[1]), "r"(a[2]), "r"(a[3]), "r"(b[0]), "r"(b[1]));
}
__device__ __forceinline__ void wsplit(bf* H, bf* L, long i, float v) {
    bf h = __float2bfloat16(v);
    H[i] = h;
    L[i] = __float2bfloat16(v - __bfloat162float(h));
}
__device__ __forceinline__ float sigf(float x) { return 1.f / (1.f + expf(-x)); }

// ------------------------- GEMM kernel --------------------------------------
// flags: 1=hasC, 2=Dm fp32, 4=hasO, 8=hasOT, 16=sym, 32=redsq, 64=Dm planes
struct GD {
    const bf *Ah, *Al, *Bh, *Bl;
    float* C;
    const float* Dm;
    const bf *DmH, *DmL;
    bf *OH, *OL, *OTH, *OTL;
    const float* betap;
    long As, Bs, Cs, Os;
    int M, N, K, csr, csc, flags;
    float alpha, beta;
};
struct TArgs {
    GD gd[5];
};

// Load a 128-row (or 64-row) x 32-half slab of a K-major plane into smem.
template <int ROWS>
__device__ __forceinline__ void ldplane(uint32_t smbase, const bf* g,
                                        int r0, int Kd, int kt, int tid) {
#pragma unroll
    for (int i = 0; i < ROWS / 64; i++) {
        int idx = tid + i * 256;
        int row = idx >> 2;
        int ch = (idx & 3) << 3;
        const bf* src = g + (long)(r0 + row) * Kd + kt + ch;
        cp16(smbase + (uint32_t)(row * AST + ch) * 2u, src);
    }
}

template <bool HALF>
__global__ __launch_bounds__(256, 2) void tgemm(const __grid_constant__ TArgs g) {
    extern __shared__ bf smh[];
    uint32_t smb = smem_u32(smh);

    constexpr int NT_ = HALF ? 64 : 128;   // CTA N-tile
    constexpr int MT_ = HALF ? 2 : 4;      // mt loop bound
    constexpr int BROWS = HALF ? 64 : 128;

    const int tid = threadIdx.x;
    const int lane = tid & 31;
    const int wid = tid >> 5;
    const int wm = HALF ? (wid >> 1) : (wid >> 2);
    const int wn = HALF ? (wid & 1) : (wid & 3);
    const int z = blockIdx.z;
    const GD& d = g.gd[z >> 3];
    const long zb = z & 7;
    const int flags = d.flags;

    int row0, col0, bi = 0, bj = 0;
    if (flags & 16) {
        int t = blockIdx.x;
        int i = 0;
        while (t >= (i + 1) * (i + 2) / 2) i++;
        bi = i; bj = t - i * (i + 1) / 2;
        row0 = bi * 128; col0 = bj * 128;
    } else {
        row0 = blockIdx.y * 128; col0 = blockIdx.x * NT_;
        if (row0 >= d.M || col0 >= d.N) return;
    }

    const bf* Ah = d.Ah + zb * d.As;
    const bf* Al = d.Al + zb * d.As;
    const bf* Bh = d.Bh + zb * d.Bs;
    const bf* Bl = d.Bl + zb * d.Bs;
    const int Kd = d.K;
    const int nslab = Kd >> 5;

    float acc[MT_][4][4];
#pragma unroll
    for (int i = 0; i < MT_; i++)
#pragma unroll
        for (int j = 0; j < 4; j++)
#pragma unroll
            for (int r = 0; r < 4; r++) acc[i][j][r] = 0.f;

    const int lrow = lane & 15;
    const int lcol = (lane >> 4) << 3;

    // prologue: stage 0
    {
        ldplane<128>(smb,                   Ah, row0, Kd, 0, tid);
        ldplane<128>(smb + PLANE_H * 2,     Al, row0, Kd, 0, tid);
        ldplane<BROWS>(smb + 2 * PLANE_H * 2, Bh, col0, Kd, 0, tid);
        ldplane<BROWS>(smb + 3 * PLANE_H * 2, Bl, col0, Kd, 0, tid);
        cp_commit();
    }

    for (int s = 0; s < nslab; s++) {
        if (s + 1 < nslab) {
            uint32_t sb = smb + (uint32_t)(((s + 1) & 1) * STAGE_H) * 2u;
            int kt = (s + 1) << 5;
            ldplane<128>(sb,                   Ah, row0, Kd, kt, tid);
            ldplane<128>(sb + PLANE_H * 2,     Al, row0, Kd, kt, tid);
            ldplane<BROWS>(sb + 2 * PLANE_H * 2, Bh, col0, Kd, kt, tid);
            ldplane<BROWS>(sb + 3 * PLANE_H * 2, Bl, col0, Kd, kt, tid);
            cp_commit();
            cp_wait<1>();
        } else {
            cp_wait<0>();
        }
        __syncthreads();

        uint32_t sb = smb + (uint32_t)((s & 1) * STAGE_H) * 2u;
#pragma unroll
        for (int k16 = 0; k16 < 2; k16++) {
            const int kh = k16 * 16 + lcol;
            uint32_t bhf[2][4], blf[2][4];
#pragma unroll
            for (int pr = 0; pr < 2; pr++) {
                int br = wn * 32 + pr * 16 + lrow;
                uint32_t off = (uint32_t)(br * AST + kh) * 2u;
                ldm4(bhf[pr], sb + 2 * PLANE_H * 2 + off);
                ldm4(blf[pr], sb + 3 * PLANE_H * 2 + off);
            }
#pragma unroll
            for (int mt = 0; mt < MT_; mt++) {
                uint32_t ahf[4], alf[4];
                int ar = wm * (16 * MT_) + mt * 16 + lrow;
                uint32_t off = (uint32_t)(ar * AST + kh) * 2u;
                ldm4(ahf, sb + off);
                ldm4(alf, sb + PLANE_H * 2 + off);
#pragma unroll
                for (int nt = 0; nt < 4; nt++) {
                    int pr = nt >> 1, hi = nt & 1;
                    uint32_t bh2[2] = {bhf[pr][hi], bhf[pr][hi + 2]};
                    uint32_t bl2[2] = {blf[pr][hi], blf[pr][hi + 2]};
                    mma16816(acc[mt][nt], ahf, bh2);
                    mma16816(acc[mt][nt], ahf, bl2);
                    mma16816(acc[mt][nt], alf, bh2);
                }
            }
        }
        __syncthreads();
    }

    // epilogue
    constexpr int TPITCH = HALF ? 65 : 129;
    float* tsb = (float*)smh;
    float* C = d.C + zb * d.Cs;
    const float* Dm = d.Dm + zb * d.Cs;
    const bf* DmH = d.DmH + zb * d.Cs;
    const bf* DmL = d.DmL + zb * d.Cs;
    bf* oh = d.OH + zb * d.Os;
    bf* ol = d.OL + zb * d.Os;
    const float bcoef = d.betap ? d.betap[zb] : d.beta;
    const int gr = lane >> 2, gc = (lane & 3) * 2;
    const int domirror = (flags & 16) && (bi != bj);
    float ssq = 0.f;
#pragma unroll
    for (int mt = 0; mt < MT_; mt++) {
#pragma unroll
        for (int nt = 0; nt < 4; nt++) {
#pragma unroll
            for (int rg = 0; rg < 4; rg++) {
                int rl = wm * (16 * MT_) + mt * 16 + gr + ((rg >> 1) << 3);
                int cl = wn * 32 + nt * 8 + gc + (rg & 1);
                int r = row0 + rl, c = col0 + cl;
                long off = (long)r * d.csr + (long)c * d.csc;
                float val = d.alpha * acc[mt][nt][rg];
                if (flags & 2) val += bcoef * Dm[off];
                if (flags & 64)
                    val += bcoef * (__bfloat162float(DmH[off]) + __bfloat162float(DmL[off]));
                if (flags & 1) C[off] = val;
                if (flags & 32) ssq += val * val;
                bf vh = __float2bfloat16(val);
                bf vl = __float2bfloat16(val - __bfloat162float(vh));
                if (flags & 4) { oh[off] = vh; ol[off] = vl; }
                if (domirror) {
                    long offm = (long)c * d.csr + (long)r * d.csc;
                    if (flags & 1) C[offm] = val;
                    if (flags & 4) { oh[offm] = vh; ol[offm] = vl; }
                }
                if (flags & 8) tsb[rl * TPITCH + cl] = val;
            }
        }
    }
    if (flags & 32) {
#pragma unroll
        for (int o = 16; o > 0; o >>= 1) ssq += __shfl_xor_sync(0xffffffffu, ssq, o);
        float* rs = (float*)smh;
        if (lane == 0) rs[wid] = ssq;
        __syncthreads();
        if (tid == 0) {
            float tot = 0.f;
#pragma unroll
            for (int w = 0; w < 8; w++) tot += rs[w];
            g_f[F_RSP + (long)z * 16 + blockIdx.y * 4 + blockIdx.x] = tot;
        }
    }
    if (flags & 8) {
        __syncthreads();
        bf* oth = d.OTH + zb * d.Os;
        bf* otl = d.OTL + zb * d.Os;
        constexpr int NITER = (128 * NT_) / 256;
#pragma unroll 4
        for (int i = 0; i < NITER; i++) {
            int idx = tid + i * 256;
            int cl = idx >> 7;
            int rl = idx & 127;
            float v = tsb[rl * TPITCH + cl];
            long off = (long)(col0 + cl) * 512 + row0 + rl;
            bf h = __float2bfloat16(v);
            oth[off] = h;
            otl[off] = __float2bfloat16(v - __bfloat162float(h));
        }
    }
}

// ------------------------- transpose/split (fp32 src -> planes) -------------
struct TSArgs {
    const float* src; long sbs; int srows, scols;
    bf *pH, *pL; long pbs;
    bf *tH, *tL; long tbs;
};
__global__ void k_tsplit(const __grid_constant__ TSArgs a) {
    __shared__ float tile[32][33];
    int z = blockIdx.z;
    const float* S = a.src + (long)z * a.sbs;
    int c0 = blockIdx.x * 32, r0 = blockIdx.y * 32;
    int tx = threadIdx.x, ty = threadIdx.y;
#pragma unroll
    for (int j = 0; j < 4; j++) {
        int r = r0 + ty + j * 8;
        float v = S[(long)r * a.scols + c0 + tx];
        tile[ty + j * 8][tx] = v;
        if (a.pH) {
            long o = (long)z * a.pbs + (long)r * a.scols + c0 + tx;
            wsplit(a.pH, a.pL, o, v);
        }
    }
    __syncthreads();
    if (a.tH) {
#pragma unroll
        for (int j = 0; j < 4; j++) {
            int c = c0 + ty + j * 8;
            float v = tile[tx][ty + j * 8];
            long o = (long)z * a.tbs + (long)c * a.srows + r0 + tx;
            wsplit(a.tH, a.tL, o, v);
        }
    }
}

// ------------------------- elementwise/fused kernels ------------------------
__global__ void k_init(const float* w0, const float* w1, const float* w2) {
    int row = blockIdx.x;
    int m = row >> 9, w = m >> 3, bh = m & 7, r = row & 511;
    const float* src = (w == 0 ? w0 : (w == 1 ? w1 : w2)) + (long)bh * MSZ + (long)r * 512;
    long mo = (long)m * MSZ + (long)r * 512;
    int t = threadIdx.x;
    float ss = 0.f;
#pragma unroll
    for (int j = 0; j < 4; j++) {
        int c = t + j * 128;
        float v = src[c];
        g_f[F_WM + mo + c] = v;
        g_f[F_WC + mo + c] = v;
        g_f[F_DM + mo + c] = 0.f;
        wsplit(g_h + H_WCH, g_h + H_WCL, mo + c, v);
        ss += v * v;
    }
    __shared__ float red[128];
    red[t] = ss; __syncthreads();
    for (int s = 64; s > 0; s >>= 1) { if (t < s) red[t] += red[t + s]; __syncthreads(); }
    if (t == 0) g_f[F_WNORM + (long)m * 512 + r] = sqrtf(red[0]);
}

__global__ void k_splitKQ(const float* kin, const float* q, int cbase) {
    long idx = blockIdx.x * 256L + threadIdx.x;
    int dd = idx & 511;
    int t = (int)((idx >> 9) & 255);
    int bh = (int)(idx >> 17);
    long so = (long)bh * TDSl + (long)(cbase + t) * DD + dd;
    wsplit(g_h + H_KH, g_h + H_KL, idx, kin[so]);
    wsplit(g_h + H_QH, g_h + H_QL, idx, q[so]);
}

__global__ void k_ew12T(const float* lr1, int cbase) {
    __shared__ float tile[32][33];
    int bh = blockIdx.z;
    int t0 = blockIdx.x * 32, di0 = blockIdx.y * 32;
    int tx = threadIdx.x, ty = threadIdx.y;
    float l1 = lr1[(long)bh * TT + cbase + t0 + tx];
#pragma unroll
    for (int j = 0; j < 4; j++) {
        long idx = (long)bh * CHB + (long)(di0 + ty + 8 * j) * CS + t0 + tx;
        float gba = g_f[F_GBA + idx], hbm = g_f[F_HBM + idx], dh = g_f[F_DHID + idx];
        float sg = sigf(gba), sil = gba * sg;
        wsplit(g_h + H_HLH, g_h + H_HLL, idx, sil * hbm * l1);
        wsplit(g_h + H_DBH, g_h + H_DBL, idx, dh * sil);
        float dgate = dh * hbm;
        wsplit(g_h + H_DGH, g_h + H_DGL, idx, dgate * sg * (1.f + gba * (1.f - sg)));
        float g0v = g_f[F_G0 + idx], hv = g_f[F_HH + idx];
        tile[ty + 8 * j][tx] = g0v * sigf(g0v) * hv;
    }
    __syncthreads();
#pragma unroll
    for (int j = 0; j < 4; j++) {
        long o = (long)bh * CHB + (long)(t0 + ty + 8 * j) * DI + di0 + tx;
        wsplit(g_h + H_GTH, g_h + H_GTL, o, tile[tx][ty + 8 * j]);
    }
}

__global__ void k_ewfwdT(int cbase) {
    __shared__ float tile[32][33];
    int bh = blockIdx.z;
    int t0 = blockIdx.x * 32, di0 = blockIdx.y * 32;
    int tx = threadIdx.x, ty = threadIdx.y;
#pragma unroll
    for (int j = 0; j < 4; j++) {
        long idx = (long)bh * CHB + (long)(di0 + ty + 8 * j) * CS + t0 + tx;
        float g0v = g_f[F_G0 + idx], hv = g_f[F_HH + idx];
        tile[ty + 8 * j][tx] = g0v * sigf(g0v) * hv;
    }
    __syncthreads();
#pragma unroll
    for (int j = 0; j < 4; j++) {
        long o = (long)bh * CHB + (long)(t0 + ty + 8 * j) * DI + di0 + tx;
        wsplit(g_h + H_GTH, g_h + H_GTL, o, tile[tx][ty + 8 * j]);
    }
}

__global__ void k_ekT(const float* kin, const float* lr0, const float* lr2, int cbase) {
    __shared__ float tile[32][33];
    int bh = blockIdx.z;
    int t0 = blockIdx.x * 32, d0 = blockIdx.y * 32;
    int tx = threadIdx.x, ty = threadIdx.y;
#pragma unroll
    for (int j = 0; j < 4; j++)
        tile[ty + 8 * j][tx] =
            kin[(long)bh * TDSl + (long)(cbase + t0 + ty + 8 * j) * DD + d0 + tx];
    __syncthreads();
    float l0 = lr0[(long)bh * TT + cbase + t0 + tx];
    float l2 = lr2[(long)bh * TT + cbase + t0 + tx];
#pragma unroll
    for (int j = 0; j < 4; j++) {
        long o = (long)bh * CHB + (long)(d0 + ty + 8 * j) * CS + t0 + tx;
        float kv = tile[tx][ty + 8 * j];
        wsplit(g_h + H_K0H, g_h + H_K0L, o, kv * l0);
        wsplit(g_h + H_K2H, g_h + H_K2L, o, kv * l2);
    }
}

__global__ void k_scalars(const float* mom, const float* mlt, int cbase) {
    int bh = blockIdx.x;
    int t = threadIdx.x;
    __shared__ float r1[256], r2[256];
    r1[t] = mom[(long)bh * TT + cbase + t];
    r2[t] = mlt[(long)bh * TT + cbase + t];
    __syncthreads();
    for (int s = 128; s > 0; s >>= 1) {
        if (t < s) { r1[t] += r1[t + s]; r2[t] += r2[t + s]; }
        __syncthreads();
    }
    if (t == 0) { g_f[F_MI + bh] = r1[0] * (1.f / CS); g_f[F_MLI + bh] = r2[0] * (1.f / CS); }
}

__global__ void k_normfin() {
    int m = threadIdx.x;  // 24
    float s = 0.f;
#pragma unroll
    for (int i = 0; i < 16; i++) s += g_f[F_RSP + (long)(m + 8) * 16 + i];
    g_f[F_RNS + m] = 1.f / (sqrtf(s) + 1e-7f);
}

__global__ void k_xsplit() {
    __shared__ float tile[32][33];
    int m = blockIdx.z;
    int c0 = blockIdx.x * 32, r0 = blockIdx.y * 32;
    int tx = threadIdx.x, ty = threadIdx.y;
    float rn = g_f[F_RNS + m];
#pragma unroll
    for (int j = 0; j < 4; j++) {
        long i = (long)m * MSZ + (long)(r0 + ty + 8 * j) * 512 + c0 + tx;
        float v = g_f[F_DM + i] * rn;
        wsplit(g_h + H_XH, g_h + H_XL, i, v);
        tile[ty + 8 * j][tx] = v;
    }
    __syncthreads();
#pragma unroll
    for (int j = 0; j < 4; j++) {
        long o = (long)m * MSZ + (long)(c0 + ty + 8 * j) * 512 + r0 + tx;
        wsplit(g_h + H_XTH, g_h + H_XTL, o, tile[tx][ty + 8 * j]);
    }
}

__global__ void k_wupd(const bf* xh, const bf* xl) {
    int row = blockIdx.x;
    int m = row >> 9, bh = m & 7, r = row & 511;
    long mo = (long)m * MSZ + (long)r * 512;
    float ml = g_f[F_MLI + bh];
    int t = threadIdx.x;
    float vals[4];
    float ss = 0.f;
#pragma unroll
    for (int j = 0; j < 4; j++) {
        int c = t + j * 128;
        float xv = __bfloat162float(xh[mo + c]) + __bfloat162float(xl[mo + c]);
        float v = g_f[F_WM + mo + c] + xv * ml;
        g_f[F_WM + mo + c] = v;
        vals[j] = v;
        ss += v * v;
    }
    __shared__ float red[128];
    red[t] = ss; __syncthreads();
    for (int s = 64; s > 0; s >>= 1) { if (t < s) red[t] += red[t + s]; __syncthreads(); }
    float scale = g_f[F_WNORM + (long)m * 512 + r] / (sqrtf(red[0]) + 1e-5f);
#pragma unroll
    for (int j = 0; j < 4; j++) {
        int c = t + j * 128;
        float w = vals[j] * scale;
        g_f[F_WC + mo + c] = w;
        wsplit(g_h + H_WCH, g_h + H_WCL, mo + c, w);
    }
}

// ------------------------- host orchestration -------------------------------
static void setgd(GD& d, const bf* Ah, const bf* Al, long As,
                  const bf* Bh, const bf* Bl, long Bs,
                  float* C, const float* Dm, const bf* DmH, const bf* DmL, long Cs,
                  bf* OH, bf* OL, bf* OTH, bf* OTL, long Os,
                  int M, int N, int K, int csr, int csc, int flags,
                  float alpha, float beta, const float* betap) {
    d.Ah = Ah; d.Al = Al; d.Bh = Bh; d.Bl = Bl;
    d.C = C; d.Dm = Dm; d.DmH = DmH; d.DmL = DmL;
    d.OH = OH; d.OL = OL; d.OTH = OTH; d.OTL = OTL;
    d.betap = betap;
    d.As = As; d.Bs = Bs; d.Cs = Cs; d.Os = Os;
    d.M = M; d.N = N; d.K = K; d.csr = csr; d.csc = csc; d.flags = flags;
    d.alpha = alpha; d.beta = beta;
}

static void ts(const float* src, long sbs, int srows, int scols,
               bf* pH, bf* pL, long pbs, bf* tH, bf* tL, long tbs, int batch) {
    TSArgs a;
    a.src = src; a.sbs = sbs; a.srows = srows; a.scols = scols;
    a.pH = pH; a.pL = pL; a.pbs = pbs;
    a.tH = tH; a.tL = tL; a.tbs = tbs;
    k_tsplit<<<dim3(scols / 32, srows / 32, batch), dim3(32, 8)>>>(a);
}

static const float NSC[5][3] = {
    {4.0848f, -6.8946f, 2.927f},
    {3.9505f, -6.3029f, 2.6377f},
    {3.7418f, -5.5913f, 2.3037f},
    {2.8769f, -3.1427f, 1.2046f},
    {2.8366f, -3.0525f, 1.2012f}};

extern "C" void kernel_launch(void* const* d_in, const int* in_sizes, int n_in,
                              void* d_out, int out_size) {
    const float* w0  = (const float*)d_in[0];
    const float* w1  = (const float*)d_in[1];
    const float* w2  = (const float*)d_in[2];
    const float* q   = (const float*)d_in[3];
    const float* kin = (const float*)d_in[4];
    const float* v   = (const float*)d_in[5];
    const float* lr0 = (const float*)d_in[6];
    const float* lr1 = (const float*)d_in[7];
    const float* lr2 = (const float*)d_in[8];
    const float* mom = (const float*)d_in[9];
    const float* mlt = (const float*)d_in[10];
    float* out = (float*)d_out;

    static int smset = 0;
    if (!smset) {
        cudaFuncSetAttribute(tgemm<false>, cudaFuncAttributeMaxDynamicSharedMemorySize, SMEM_TOTAL);
        cudaFuncSetAttribute(tgemm<true>, cudaFuncAttributeMaxDynamicSharedMemorySize, SMEM_TOTAL);
        smset = 1;
    }

    float* F;
    bf* H;
    cudaGetSymbolAddress((void**)&F, g_f);
    cudaGetSymbolAddress((void**)&H, g_h);

    k_init<<<NMAT * 512, 128>>>(w0, w1, w2);
    ts(F + F_WC + 8L * MSZ, MSZ, 512, 512, 0, 0, 0, H + H_W1TH, H + H_W1TL, MSZ, 8);

    for (int ci = 0; ci < NCHUNK; ci++) {
        int cb = ci * CS;

        k_scalars<<<BH, 256>>>(mom, mlt, cb);
        k_splitKQ<<<(int)(CHT / 256), 256>>>(kin, q, cb);
        ts(v + (long)cb * DD, TDSl, 256, 512,
           H + H_VH, H + H_VL, CHB, H + H_VTH, H + H_VTL, CHB, 8);

        // activation GEMMs: 5 groups of 8, half-N tiles for wave packing
        {
            TArgs g;
            setgd(g.gd[0], H + H_WCH, H + H_WCL, MSZ, H + H_KH, H + H_KL, CHB,
                  F + F_GBA, 0, 0, 0, CHB, 0, 0, 0, 0, 0,
                  512, 256, 512, CS, 1, 1, 1.f, 0.f, 0);
            setgd(g.gd[1], H + H_WCH + 16L * MSZ, H + H_WCL + 16L * MSZ, MSZ,
                  H + H_KH, H + H_KL, CHB, F + F_HBM, 0, 0, 0, CHB, 0, 0, 0, 0, 0,
                  512, 256, 512, CS, 1, 1, 1.f, 0.f, 0);
            setgd(g.gd[2], H + H_WCH + 16L * MSZ, H + H_WCL + 16L * MSZ, MSZ,
                  H + H_QH, H + H_QL, CHB, F + F_HH, 0, 0, 0, CHB, 0, 0, 0, 0, 0,
                  512, 256, 512, CS, 1, 1, 1.f, 0.f, 0);
            setgd(g.gd[3], H + H_WCH, H + H_WCL, MSZ, H + H_QH, H + H_QL, CHB,
                  F + F_G0, 0, 0, 0, CHB, 0, 0, 0, 0, 0,
                  512, 256, 512, CS, 1, 1, 1.f, 0.f, 0);
            setgd(g.gd[4], H + H_W1TH, H + H_W1TL, MSZ, H + H_VH, H + H_VL, CHB,
                  F + F_DHID, 0, 0, 0, CHB, 0, 0, 0, 0, 0,
                  512, 256, 512, CS, 1, 1, 1.f, 0.f, 0);
            tgemm<true><<<dim3(4, 4, 40), 256, SMEM_TOTAL>>>(g);
        }

        k_ew12T<<<dim3(8, 16, 8), dim3(32, 8)>>>(lr1, cb);
        k_ekT<<<dim3(8, 16, 8), dim3(32, 8)>>>(kin, lr0, lr2, cb);

        // merged: out GEMM + dw GEMMs (full tiles; sumsq partials use 4x4 grid)
        {
            TArgs g;
            setgd(g.gd[0], H + H_WCH + 8L * MSZ, H + H_WCL + 8L * MSZ, MSZ,
                  H + H_GTH, H + H_GTL, CHB,
                  out + (long)cb * DD, 0, 0, 0, TDSl, 0, 0, 0, 0, 0,
                  512, 256, 512, 1, DD, 1, 1.f, 0.f, 0);
            setgd(g.gd[1], H + H_DGH, H + H_DGL, CHB, H + H_K0H, H + H_K0L, CHB,
                  F + F_DM, F + F_DM, 0, 0, MSZ, 0, 0, 0, 0, 0,
                  512, 512, 256, 512, 1, 1 | 2 | 32, 1.f, 0.f, F + F_MI);
            setgd(g.gd[2], H + H_VTH, H + H_VTL, CHB, H + H_HLH, H + H_HLL, CHB,
                  F + F_DM + 8L * MSZ, F + F_DM + 8L * MSZ, 0, 0, MSZ, 0, 0, 0, 0, 0,
                  512, 512, 256, 512, 1, 1 | 2 | 32, 1.f, 0.f, F + F_MI);
            setgd(g.gd[3], H + H_DBH, H + H_DBL, CHB, H + H_K2H, H + H_K2L, CHB,
                  F + F_DM + 16L * MSZ, F + F_DM + 16L * MSZ, 0, 0, MSZ, 0, 0, 0, 0, 0,
                  512, 512, 256, 512, 1, 1 | 2 | 32, 1.f, 0.f, F + F_MI);
            tgemm<false><<<dim3(4, 4, 32), 256, SMEM_TOTAL>>>(g);
        }

        k_normfin<<<1, 24>>>();
        k_xsplit<<<dim3(16, 16, 24), dim3(32, 8)>>>();

        // Newton-Schulz (5 iters); X and XT planes ping-pong
        for (int it = 0; it < 5; it++) {
            float aa = NSC[it][0], bb = NSC[it][1], cc = NSC[it][2];
            long xA_h  = (it & 1) ? H_X2H : H_XH;
            long xA_l  = (it & 1) ? H_X2L : H_XL;
            long xB_h  = (it & 1) ? H_XH : H_X2H;
            long xB_l  = (it & 1) ? H_XL : H_X2L;
            long xtA_h = (it & 1) ? H_XT2H : H_XTH;
            long xtA_l = (it & 1) ? H_XT2L : H_XTL;
            long xtB_h = (it & 1) ? H_XTH : H_XT2H;
            long xtB_l = (it & 1) ? H_XTL : H_XT2L;
            // A = X @ X^T : symmetric triangle (full tiles)
            {
                TArgs g;
                for (int j = 0; j < 3; j++) {
                    long mb = (long)j * 8 * MSZ;
                    setgd(g.gd[j], H + xA_h + mb, H + xA_l + mb, MSZ,
                          H + xA_h + mb, H + xA_l + mb, MSZ,
                          0, 0, 0, 0, MSZ,
                          H + H_AH + mb, H + H_AL + mb, 0, 0, MSZ,
                          512, 512, 512, 512, 1, 4 | 16, 1.f, 0.f, 0);
                }
                tgemm<false><<<dim3(10, 1, 24), 256, SMEM_TOTAL>>>(g);
            }
            // B = b*A + c*(A@A) : symmetric triangle, beta from A planes
            {
                TArgs g;
                for (int j = 0; j < 3; j++) {
                    long mb = (long)j * 8 * MSZ;
                    setgd(g.gd[j], H + H_AH + mb, H + H_AL + mb, MSZ,
                          H + H_AH + mb, H + H_AL + mb, MSZ,
                          0, 0, H + H_AH + mb, H + H_AL + mb, MSZ,
                          H + H_BH + mb, H + H_BL + mb, 0, 0, MSZ,
                          512, 512, 512, 512, 1, 4 | 16 | 64, cc, bb, 0);
                }
                tgemm<false><<<dim3(10, 1, 24), 256, SMEM_TOTAL>>>(g);
            }
            // X' = a*X + B@X : half-N tiles for wave packing
            {
                TArgs g;
                for (int j = 0; j < 3; j++) {
                    long mb = (long)j * 8 * MSZ;
                    setgd(g.gd[j], H + H_BH + mb, H + H_BL + mb, MSZ,
                          H + xtA_h + mb, H + xtA_l + mb, MSZ,
                          0, 0, H + xA_h + mb, H + xA_l + mb, MSZ,
                          H + xB_h + mb, H + xB_l + mb,
                          H + xtB_h + mb, H + xtB_l + mb, MSZ,
                          512, 512, 512, 512, 1, 4 | 8 | 64, 1.f, aa, 0);
                }
                tgemm<true><<<dim3(8, 4, 24), 256, SMEM_TOTAL>>>(g);
            }
        }

        k_wupd<<<NMAT * 512, 128>>>(H + H_X2H, H + H_X2L);
        ts(F + F_WC + 8L * MSZ, MSZ, 512, 512, 0, 0, 0, H + H_W1TH, H + H_W1TL, MSZ, 8);
    }

    // final forward-only chunk
    {
        int cb = NCHUNK * CS;
        k_splitKQ<<<(int)(CHT / 256), 256>>>(kin, q, cb);
        {
            TArgs g;
            setgd(g.gd[0], H + H_WCH + 16L * MSZ, H + H_WCL + 16L * MSZ, MSZ,
                  H + H_QH, H + H_QL, CHB, F + F_HH, 0, 0, 0, CHB, 0, 0, 0, 0, 0,
                  512, 256, 512, CS, 1, 1, 1.f, 0.f, 0);
            setgd(g.gd[1], H + H_WCH, H + H_WCL, MSZ, H + H_QH, H + H_QL, CHB,
                  F + F_G0, 0, 0, 0, CHB, 0, 0, 0, 0, 0,
                  512, 256, 512, CS, 1, 1, 1.f, 0.f, 0);
            tgemm<true><<<dim3(4, 4, 16), 256, SMEM_TOTAL>>>(g);
        }
        k_ewfwdT<<<dim3(8, 16, 8), dim3(32, 8)>>>(cb);
        {
            TArgs g;
            setgd(g.gd[0], H + H_WCH + 8L * MSZ, H + H_WCL + 8L * MSZ, MSZ,
                  H + H_GTH, H + H_GTL, CHB,
                  out + (long)cb * DD, 0, 0, 0, TDSl, 0, 0, 0, 0, 0,
                  512, 256, 512, 1, DD, 1, 1.f, 0.f, 0);
            tgemm<true><<<dim3(4, 4, 8), 256, SMEM_TOTAL>>>(g);
        }
    }
}

// round 14
// speedup vs baseline: 1.0388x; 1.0388x over previous
#include <cuda_runtime.h>
#include <cuda_bf16.h>
#include <math.h>
#include <stdint.h>

// ---------------------------------------------------------------------------
// LaCT SWIGLU fast-weight attention — mma.sync bf16-split-3 GEMM engine v3.4.
// v3.2 (full 128x128 tiles everywhere — R13's half-N tiles reverted: per-CTA
// cost ~0.75T, makespan worse) + k_pre single-launch pre-GEMM elementwise
// (splitKQ + V split/T + k*lr planes + scalars) + rns recompute fused into
// k_xsplit (normfin launch removed).
// ---------------------------------------------------------------------------

#define BH 8
#define TT 4096
#define DD 512
#define DI 512
#define CS 256
#define NCHUNK 15
#define NMAT 24
#define MSZ (512 * 512)
#define AST 40
#define PLANE_H (128 * AST)
#define STAGE_H (4 * PLANE_H)
#define NSTAGE 2
#define SMEM_TOTAL (NSTAGE * STAGE_H * 2)  // 81920 bytes

static constexpr long NM_  = (long)NMAT * MSZ;
static constexpr long W1M_ = 8L * MSZ;
static constexpr long CHB  = (long)CS * DD;
static constexpr long CHT  = (long)BH * CHB;
static constexpr long TDSl = (long)TT * DD;

// fp32 heap
static constexpr long F_WM = 0, F_WC = NM_, F_DM = 2 * NM_;
static constexpr long F_GBA = 3 * NM_, F_HBM = F_GBA + CHT, F_HH = F_HBM + CHT,
                      F_G0 = F_HH + CHT, F_DHID = F_G0 + CHT;
static constexpr long F_WNORM = F_DHID + CHT, F_MI = F_WNORM + NMAT * 512L,
                      F_MLI = F_MI + 8, F_RNS = F_MLI + 8,
                      F_RSP = F_RNS + NMAT, F_TOT = F_RSP + 512;
__device__ __align__(256) float g_f[F_TOT];

// bf16 heap
static constexpr long H_WCH = 0, H_WCL = NM_,
                      H_W1TH = 2 * NM_, H_W1TL = H_W1TH + W1M_,
                      H_XH = H_W1TL + W1M_, H_XL = H_XH + NM_,
                      H_X2H = H_XL + NM_, H_X2L = H_X2H + NM_,
                      H_XTH = H_X2L + NM_, H_XTL = H_XTH + NM_,
                      H_XT2H = H_XTL + NM_, H_XT2L = H_XT2H + NM_,
                      H_AH = H_XT2L + NM_, H_AL = H_AH + NM_,
                      H_BH = H_AL + NM_, H_BL = H_BH + NM_;
static constexpr long H_KH = H_BL + NM_, H_KL = H_KH + CHT, H_QH = H_KL + CHT,
                      H_QL = H_QH + CHT, H_VH = H_QL + CHT, H_VL = H_VH + CHT,
                      H_VTH = H_VL + CHT, H_VTL = H_VTH + CHT,
                      H_K0H = H_VTL + CHT, H_K0L = H_K0H + CHT,
                      H_K2H = H_K0L + CHT, H_K2L = H_K2H + CHT,
                      H_GTH = H_K2L + CHT, H_GTL = H_GTH + CHT,
                      H_HLH = H_GTL + CHT, H_HLL = H_HLH + CHT,
                      H_DGH = H_HLL + CHT, H_DGL = H_DGH + CHT,
                      H_DBH = H_DGL + CHT, H_DBL = H_DBH + CHT,
                      H_TOT = H_DBL + CHT;
__device__ __align__(256) __nv_bfloat16 g_h[H_TOT];

typedef __nv_bfloat16 bf;

// ------------------------- helpers -----------------------------------------
__device__ __forceinline__ uint32_t smem_u32(const void* p) {
    uint32_t a;
    asm("{ .reg .u64 t; cvta.to.shared.u64 t, %1; cvt.u32.u64 %0, t; }" : "=r"(a) : "l"(p));
    return a;
}
__device__ __forceinline__ void cp16(uint32_t dst, const void* src) {
    asm volatile("cp.async.cg.shared.global [%0], [%1], 16;" :: "r"(dst), "l"(src));
}
__device__ __forceinline__ void cp_commit() {
    asm volatile("cp.async.commit_group;" ::: "memory");
}
template <int N>
__device__ __forceinline__ void cp_wait() {
    asm volatile("cp.async.wait_group %0;" :: "n"(N) : "memory");
}
__device__ __forceinline__ void ldm4(uint32_t* f, uint32_t addr) {
    asm volatile("ldmatrix.sync.aligned.m8n8.x4.shared.b16 {%0,%1,%2,%3}, [%4];"
                 : "=r"(f[0]), "=r"(f[1]), "=r"(f[2]), "=r"(f[3]) : "r"(addr));
}
__device__ __forceinline__ void mma16816(float* c, const uint32_t* a, const uint32_t* b) {
    asm volatile("mma.sync.aligned.m16n8k16.row.col.f32.bf16.bf16.f32 "
                 "{%0,%1,%2,%3}, {%4,%5,%6,%7}, {%8,%9}, {%0,%1,%2,%3};"
                 : "+f"(c[0]), "+f"(c[1]), "+f"(c[2]), "+f"(c[3])
                 : "r"(a[0]), "r"(a[1]), "r"(a[2]), "r"(a[3]), "r"(b[0]), "r"(b[1]));
}
__device__ __forceinline__ void wsplit(bf* H, bf* L, long i, float v) {
    bf h = __float2bfloat16(v);
    H[i] = h;
    L[i] = __float2bfloat16(v - __bfloat162float(h));
}
__device__ __forceinline__ float sigf(float x) { return 1.f / (1.f + expf(-x)); }

// ------------------------- GEMM kernel --------------------------------------
// flags: 1=hasC, 2=Dm fp32, 4=hasO, 8=hasOT, 16=sym, 32=redsq, 64=Dm planes
struct GD {
    const bf *Ah, *Al, *Bh, *Bl;
    float* C;
    const float* Dm;
    const bf *DmH, *DmL;
    bf *OH, *OL, *OTH, *OTL;
    const float* betap;
    long As, Bs, Cs, Os;
    int M, N, K, csr, csc, flags;
    float alpha, beta;
};
struct TArgs {
    GD gd[5];
};

__device__ __forceinline__ void ldplane(uint32_t smbase, const bf* g,
                                        int r0, int Kd, int kt, int tid) {
#pragma unroll
    for (int i = 0; i < 2; i++) {
        int idx = tid + i * 256;
        int row = idx >> 2;
        int ch = (idx & 3) << 3;
        const bf* src = g + (long)(r0 + row) * Kd + kt + ch;
        cp16(smbase + (uint32_t)(row * AST + ch) * 2u, src);
    }
}

__global__ __launch_bounds__(256, 2) void tgemm(const __grid_constant__ TArgs g) {
    extern __shared__ bf smh[];
    uint32_t smb = smem_u32(smh);

    const int tid = threadIdx.x;
    const int lane = tid & 31;
    const int wid = tid >> 5;
    const int wm = wid >> 2;
    const int wn = wid & 3;
    const int z = blockIdx.z;
    const GD& d = g.gd[z >> 3];
    const long zb = z & 7;
    const int flags = d.flags;

    int row0, col0, bi = 0, bj = 0;
    if (flags & 16) {
        int t = blockIdx.x;
        int i = 0;
        while (t >= (i + 1) * (i + 2) / 2) i++;
        bi = i; bj = t - i * (i + 1) / 2;
        row0 = bi * 128; col0 = bj * 128;
    } else {
        row0 = blockIdx.y * 128; col0 = blockIdx.x * 128;
        if (row0 >= d.M || col0 >= d.N) return;
    }

    const bf* Ah = d.Ah + zb * d.As;
    const bf* Al = d.Al + zb * d.As;
    const bf* Bh = d.Bh + zb * d.Bs;
    const bf* Bl = d.Bl + zb * d.Bs;
    const int Kd = d.K;
    const int nslab = Kd >> 5;

    float acc[4][4][4];
#pragma unroll
    for (int i = 0; i < 4; i++)
#pragma unroll
        for (int j = 0; j < 4; j++)
#pragma unroll
            for (int r = 0; r < 4; r++) acc[i][j][r] = 0.f;

    const int lrow = lane & 15;
    const int lcol = (lane >> 4) << 3;

    // prologue: stage 0
    {
        ldplane(smb,                   Ah, row0, Kd, 0, tid);
        ldplane(smb + PLANE_H * 2,     Al, row0, Kd, 0, tid);
        ldplane(smb + 2 * PLANE_H * 2, Bh, col0, Kd, 0, tid);
        ldplane(smb + 3 * PLANE_H * 2, Bl, col0, Kd, 0, tid);
        cp_commit();
    }

    for (int s = 0; s < nslab; s++) {
        if (s + 1 < nslab) {
            uint32_t sb = smb + (uint32_t)(((s + 1) & 1) * STAGE_H) * 2u;
            int kt = (s + 1) << 5;
            ldplane(sb,                   Ah, row0, Kd, kt, tid);
            ldplane(sb + PLANE_H * 2,     Al, row0, Kd, kt, tid);
            ldplane(sb + 2 * PLANE_H * 2, Bh, col0, Kd, kt, tid);
            ldplane(sb + 3 * PLANE_H * 2, Bl, col0, Kd, kt, tid);
            cp_commit();
            cp_wait<1>();
        } else {
            cp_wait<0>();
        }
        __syncthreads();

        uint32_t sb = smb + (uint32_t)((s & 1) * STAGE_H) * 2u;
#pragma unroll
        for (int k16 = 0; k16 < 2; k16++) {
            const int kh = k16 * 16 + lcol;
            uint32_t bhf[2][4], blf[2][4];
#pragma unroll
            for (int pr = 0; pr < 2; pr++) {
                int br = wn * 32 + pr * 16 + lrow;
                uint32_t off = (uint32_t)(br * AST + kh) * 2u;
                ldm4(bhf[pr], sb + 2 * PLANE_H * 2 + off);
                ldm4(blf[pr], sb + 3 * PLANE_H * 2 + off);
            }
#pragma unroll
            for (int mt = 0; mt < 4; mt++) {
                uint32_t ahf[4], alf[4];
                int ar = wm * 64 + mt * 16 + lrow;
                uint32_t off = (uint32_t)(ar * AST + kh) * 2u;
                ldm4(ahf, sb + off);
                ldm4(alf, sb + PLANE_H * 2 + off);
#pragma unroll
                for (int nt = 0; nt < 4; nt++) {
                    int pr = nt >> 1, hi = nt & 1;
                    uint32_t bh2[2] = {bhf[pr][hi], bhf[pr][hi + 2]};
                    uint32_t bl2[2] = {blf[pr][hi], blf[pr][hi + 2]};
                    mma16816(acc[mt][nt], ahf, bh2);
                    mma16816(acc[mt][nt], ahf, bl2);
                    mma16816(acc[mt][nt], alf, bh2);
                }
            }
        }
        __syncthreads();
    }

    // epilogue
    float* tsb = (float*)smh;
    float* C = d.C + zb * d.Cs;
    const float* Dm = d.Dm + zb * d.Cs;
    const bf* DmH = d.DmH + zb * d.Cs;
    const bf* DmL = d.DmL + zb * d.Cs;
    bf* oh = d.OH + zb * d.Os;
    bf* ol = d.OL + zb * d.Os;
    const float bcoef = d.betap ? d.betap[zb] : d.beta;
    const int gr = lane >> 2, gc = (lane & 3) * 2;
    const int domirror = (flags & 16) && (bi != bj);
    float ssq = 0.f;
#pragma unroll
    for (int mt = 0; mt < 4; mt++) {
#pragma unroll
        for (int nt = 0; nt < 4; nt++) {
#pragma unroll
            for (int rg = 0; rg < 4; rg++) {
                int rl = wm * 64 + mt * 16 + gr + ((rg >> 1) << 3);
                int cl = wn * 32 + nt * 8 + gc + (rg & 1);
                int r = row0 + rl, c = col0 + cl;
                long off = (long)r * d.csr + (long)c * d.csc;
                float val = d.alpha * acc[mt][nt][rg];
                if (flags & 2) val += bcoef * Dm[off];
                if (flags & 64)
                    val += bcoef * (__bfloat162float(DmH[off]) + __bfloat162float(DmL[off]));
                if (flags & 1) C[off] = val;
                if (flags & 32) ssq += val * val;
                bf vh = __float2bfloat16(val);
                bf vl = __float2bfloat16(val - __bfloat162float(vh));
                if (flags & 4) { oh[off] = vh; ol[off] = vl; }
                if (domirror) {
                    long offm = (long)c * d.csr + (long)r * d.csc;
                    if (flags & 1) C[offm] = val;
                    if (flags & 4) { oh[offm] = vh; ol[offm] = vl; }
                }
                if (flags & 8) tsb[rl * 129 + cl] = val;
            }
        }
    }
    if (flags & 32) {
#pragma unroll
        for (int o = 16; o > 0; o >>= 1) ssq += __shfl_xor_sync(0xffffffffu, ssq, o);
        float* rs = (float*)smh;
        if (lane == 0) rs[wid] = ssq;
        __syncthreads();
        if (tid == 0) {
            float tot = 0.f;
#pragma unroll
            for (int w = 0; w < 8; w++) tot += rs[w];
            g_f[F_RSP + (long)z * 16 + blockIdx.y * 4 + blockIdx.x] = tot;
        }
    }
    if (flags & 8) {
        __syncthreads();
        bf* oth = d.OTH + zb * d.Os;
        bf* otl = d.OTL + zb * d.Os;
#pragma unroll 4
        for (int i = 0; i < 64; i++) {
            int idx = tid + i * 256;
            int cl = idx >> 7;
            int rl = idx & 127;
            float v = tsb[rl * 129 + cl];
            long off = (long)(col0 + cl) * 512 + row0 + rl;
            bf h = __float2bfloat16(v);
            oth[off] = h;
            otl[off] = __float2bfloat16(v - __bfloat162float(h));
        }
    }
}

// ------------------------- transpose/split (fp32 src -> planes) -------------
struct TSArgs {
    const float* src; long sbs; int srows, scols;
    bf *pH, *pL; long pbs;
    bf *tH, *tL; long tbs;
};
__global__ void k_tsplit(const __grid_constant__ TSArgs a) {
    __shared__ float tile[32][33];
    int z = blockIdx.z;
    const float* S = a.src + (long)z * a.sbs;
    int c0 = blockIdx.x * 32, r0 = blockIdx.y * 32;
    int tx = threadIdx.x, ty = threadIdx.y;
#pragma unroll
    for (int j = 0; j < 4; j++) {
        int r = r0 + ty + j * 8;
        float v = S[(long)r * a.scols + c0 + tx];
        tile[ty + j * 8][tx] = v;
        if (a.pH) {
            long o = (long)z * a.pbs + (long)r * a.scols + c0 + tx;
            wsplit(a.pH, a.pL, o, v);
        }
    }
    __syncthreads();
    if (a.tH) {
#pragma unroll
        for (int j = 0; j < 4; j++) {
            int c = c0 + ty + j * 8;
            float v = tile[tx][ty + j * 8];
            long o = (long)z * a.tbs + (long)c * a.srows + r0 + tx;
            wsplit(a.tH, a.tL, o, v);
        }
    }
}

// ------------------------- elementwise/fused kernels ------------------------
__global__ void k_init(const float* w0, const float* w1, const float* w2) {
    int row = blockIdx.x;
    int m = row >> 9, w = m >> 3, bh = m & 7, r = row & 511;
    const float* src = (w == 0 ? w0 : (w == 1 ? w1 : w2)) + (long)bh * MSZ + (long)r * 512;
    long mo = (long)m * MSZ + (long)r * 512;
    int t = threadIdx.x;
    float ss = 0.f;
#pragma unroll
    for (int j = 0; j < 4; j++) {
        int c = t + j * 128;
        float v = src[c];
        g_f[F_WM + mo + c] = v;
        g_f[F_WC + mo + c] = v;
        g_f[F_DM + mo + c] = 0.f;
        wsplit(g_h + H_WCH, g_h + H_WCL, mo + c, v);
        ss += v * v;
    }
    __shared__ float red[128];
    red[t] = ss; __syncthreads();
    for (int s = 64; s > 0; s >>= 1) { if (t < s) red[t] += red[t + s]; __syncthreads(); }
    if (t == 0) g_f[F_WNORM + (long)m * 512 + r] = sqrtf(red[0]);
}

// one launch: splitKQ (512 blk/bh) + V split/T (128) + k*lr planes (128) + scalars (1)
__global__ void k_pre(const float* kin, const float* q, const float* v,
                      const float* lr0, const float* lr2,
                      const float* mom, const float* mlt, int cbase) {
    __shared__ float tile[32][33];
    int bh = blockIdx.z;
    int b = blockIdx.x;
    int tid = threadIdx.x;
    if (b < 512) {
        // splitKQ
        long idx = ((long)bh << 17) + b * 256L + tid;
        int dd = idx & 511;
        int t = (int)((idx >> 9) & 255);
        long so = (long)bh * TDSl + (long)(cbase + t) * DD + dd;
        wsplit(g_h + H_KH, g_h + H_KL, idx, kin[so]);
        wsplit(g_h + H_QH, g_h + H_QL, idx, q[so]);
        return;
    }
    int tx = tid & 31, ty = tid >> 5;
    if (b < 640) {
        // V split + transpose: tile c0 over 512, r0 over 256
        int bb = b - 512;                  // 0..127, grid (16 x, 8 y)
        int c0 = (bb & 15) * 32, r0 = (bb >> 4) * 32;
        const float* S = v + (long)bh * TDSl + (long)cbase * DD;
#pragma unroll
        for (int j = 0; j < 4; j++) {
            int r = r0 + ty + j * 8;
            float val = S[(long)r * DD + c0 + tx];
            tile[ty + j * 8][tx] = val;
            long o = (long)bh * CHB + (long)r * DD + c0 + tx;
            wsplit(g_h + H_VH, g_h + H_VL, o, val);
        }
        __syncthreads();
#pragma unroll
        for (int j = 0; j < 4; j++) {
            int c = c0 + ty + j * 8;
            float val = tile[tx][ty + j * 8];
            long o = (long)bh * CHB + (long)c * CS + r0 + tx;
            wsplit(g_h + H_VTH, g_h + H_VTL, o, val);
        }
        return;
    }
    if (b < 768) {
        // k*lr -> transposed K0/K2 planes: (t0 over 256 x8, d0 over 512 x16)
        int bb = b - 640;
        int t0 = (bb & 7) * 32, d0 = (bb >> 3) * 32;
#pragma unroll
        for (int j = 0; j < 4; j++)
            tile[ty + 8 * j][tx] =
                kin[(long)bh * TDSl + (long)(cbase + t0 + ty + 8 * j) * DD + d0 + tx];
        __syncthreads();
        float l0 = lr0[(long)bh * TT + cbase + t0 + tx];
        float l2 = lr2[(long)bh * TT + cbase + t0 + tx];
#pragma unroll
        for (int j = 0; j < 4; j++) {
            long o = (long)bh * CHB + (long)(d0 + ty + 8 * j) * CS + t0 + tx;
            float kv = tile[tx][ty + 8 * j];
            wsplit(g_h + H_K0H, g_h + H_K0L, o, kv * l0);
            wsplit(g_h + H_K2H, g_h + H_K2L, o, kv * l2);
        }
        return;
    }
    {
        // scalars (1 block per bh)
        __shared__ float r1[256], r2[256];
        r1[tid] = mom[(long)bh * TT + cbase + tid];
        r2[tid] = mlt[(long)bh * TT + cbase + tid];
        __syncthreads();
        for (int s = 128; s > 0; s >>= 1) {
            if (tid < s) { r1[tid] += r1[tid + s]; r2[tid] += r2[tid + s]; }
            __syncthreads();
        }
        if (tid == 0) {
            g_f[F_MI + bh] = r1[0] * (1.f / CS);
            g_f[F_MLI + bh] = r2[0] * (1.f / CS);
        }
    }
}

__global__ void k_splitKQ(const float* kin, const float* q, int cbase) {
    long idx = blockIdx.x * 256L + threadIdx.x;
    int dd = idx & 511;
    int t = (int)((idx >> 9) & 255);
    int bh = (int)(idx >> 17);
    long so = (long)bh * TDSl + (long)(cbase + t) * DD + dd;
    wsplit(g_h + H_KH, g_h + H_KL, idx, kin[so]);
    wsplit(g_h + H_QH, g_h + H_QL, idx, q[so]);
}

__global__ void k_ew12T(const float* lr1, int cbase) {
    __shared__ float tile[32][33];
    int bh = blockIdx.z;
    int t0 = blockIdx.x * 32, di0 = blockIdx.y * 32;
    int tx = threadIdx.x, ty = threadIdx.y;
    float l1 = lr1[(long)bh * TT + cbase + t0 + tx];
#pragma unroll
    for (int j = 0; j < 4; j++) {
        long idx = (long)bh * CHB + (long)(di0 + ty + 8 * j) * CS + t0 + tx;
        float gba = g_f[F_GBA + idx], hbm = g_f[F_HBM + idx], dh = g_f[F_DHID + idx];
        float sg = sigf(gba), sil = gba * sg;
        wsplit(g_h + H_HLH, g_h + H_HLL, idx, sil * hbm * l1);
        wsplit(g_h + H_DBH, g_h + H_DBL, idx, dh * sil);
        float dgate = dh * hbm;
        wsplit(g_h + H_DGH, g_h + H_DGL, idx, dgate * sg * (1.f + gba * (1.f - sg)));
        float g0v = g_f[F_G0 + idx], hv = g_f[F_HH + idx];
        tile[ty + 8 * j][tx] = g0v * sigf(g0v) * hv;
    }
    __syncthreads();
#pragma unroll
    for (int j = 0; j < 4; j++) {
        long o = (long)bh * CHB + (long)(t0 + ty + 8 * j) * DI + di0 + tx;
        wsplit(g_h + H_GTH, g_h + H_GTL, o, tile[tx][ty + 8 * j]);
    }
}

__global__ void k_ewfwdT(int cbase) {
    __shared__ float tile[32][33];
    int bh = blockIdx.z;
    int t0 = blockIdx.x * 32, di0 = blockIdx.y * 32;
    int tx = threadIdx.x, ty = threadIdx.y;
#pragma unroll
    for (int j = 0; j < 4; j++) {
        long idx = (long)bh * CHB + (long)(di0 + ty + 8 * j) * CS + t0 + tx;
        float g0v = g_f[F_G0 + idx], hv = g_f[F_HH + idx];
        tile[ty + 8 * j][tx] = g0v * sigf(g0v) * hv;
    }
    __syncthreads();
#pragma unroll
    for (int j = 0; j < 4; j++) {
        long o = (long)bh * CHB + (long)(t0 + ty + 8 * j) * DI + di0 + tx;
        wsplit(g_h + H_GTH, g_h + H_GTL, o, tile[tx][ty + 8 * j]);
    }
}

// dm*rns -> X planes (pair 0) + XT planes (pair 0); rns computed in-block
__global__ void k_xsplit() {
    __shared__ float tile[32][33];
    __shared__ float rns_s;
    int m = blockIdx.z;
    int c0 = blockIdx.x * 32, r0 = blockIdx.y * 32;
    int tx = threadIdx.x, ty = threadIdx.y;
    if (tx == 0 && ty == 0) {
        float s = 0.f;
#pragma unroll
        for (int i = 0; i < 16; i++) s += g_f[F_RSP + (long)(m + 8) * 16 + i];
        rns_s = 1.f / (sqrtf(s) + 1e-7f);
    }
    __syncthreads();
    float rn = rns_s;
#pragma unroll
    for (int j = 0; j < 4; j++) {
        long i = (long)m * MSZ + (long)(r0 + ty + 8 * j) * 512 + c0 + tx;
        float v = g_f[F_DM + i] * rn;
        wsplit(g_h + H_XH, g_h + H_XL, i, v);
        tile[ty + 8 * j][tx] = v;
    }
    __syncthreads();
#pragma unroll
    for (int j = 0; j < 4; j++) {
        long o = (long)m * MSZ + (long)(c0 + ty + 8 * j) * 512 + r0 + tx;
        wsplit(g_h + H_XTH, g_h + H_XTL, o, tile[tx][ty + 8 * j]);
    }
}

__global__ void k_wupd(const bf* xh, const bf* xl) {
    int row = blockIdx.x;
    int m = row >> 9, bh = m & 7, r = row & 511;
    long mo = (long)m * MSZ + (long)r * 512;
    float ml = g_f[F_MLI + bh];
    int t = threadIdx.x;
    float vals[4];
    float ss = 0.f;
#pragma unroll
    for (int j = 0; j < 4; j++) {
        int c = t + j * 128;
        float xv = __bfloat162float(xh[mo + c]) + __bfloat162float(xl[mo + c]);
        float v = g_f[F_WM + mo + c] + xv * ml;
        g_f[F_WM + mo + c] = v;
        vals[j] = v;
        ss += v * v;
    }
    __shared__ float red[128];
    red[t] = ss; __syncthreads();
    for (int s = 64; s > 0; s >>= 1) { if (t < s) red[t] += red[t + s]; __syncthreads(); }
    float scale = g_f[F_WNORM + (long)m * 512 + r] / (sqrtf(red[0]) + 1e-5f);
#pragma unroll
    for (int j = 0; j < 4; j++) {
        int c = t + j * 128;
        float w = vals[j] * scale;
        g_f[F_WC + mo + c] = w;
        wsplit(g_h + H_WCH, g_h + H_WCL, mo + c, w);
    }
}

// ------------------------- host orchestration -------------------------------
static void setgd(GD& d, const bf* Ah, const bf* Al, long As,
                  const bf* Bh, const bf* Bl, long Bs,
                  float* C, const float* Dm, const bf* DmH, const bf* DmL, long Cs,
                  bf* OH, bf* OL, bf* OTH, bf* OTL, long Os,
                  int M, int N, int K, int csr, int csc, int flags,
                  float alpha, float beta, const float* betap) {
    d.Ah = Ah; d.Al = Al; d.Bh = Bh; d.Bl = Bl;
    d.C = C; d.Dm = Dm; d.DmH = DmH; d.DmL = DmL;
    d.OH = OH; d.OL = OL; d.OTH = OTH; d.OTL = OTL;
    d.betap = betap;
    d.As = As; d.Bs = Bs; d.Cs = Cs; d.Os = Os;
    d.M = M; d.N = N; d.K = K; d.csr = csr; d.csc = csc; d.flags = flags;
    d.alpha = alpha; d.beta = beta;
}

static void ts(const float* src, long sbs, int srows, int scols,
               bf* pH, bf* pL, long pbs, bf* tH, bf* tL, long tbs, int batch) {
    TSArgs a;
    a.src = src; a.sbs = sbs; a.srows = srows; a.scols = scols;
    a.pH = pH; a.pL = pL; a.pbs = pbs;
    a.tH = tH; a.tL = tL; a.tbs = tbs;
    k_tsplit<<<dim3(scols / 32, srows / 32, batch), dim3(32, 8)>>>(a);
}

static const float NSC[5][3] = {
    {4.0848f, -6.8946f, 2.927f},
    {3.9505f, -6.3029f, 2.6377f},
    {3.7418f, -5.5913f, 2.3037f},
    {2.8769f, -3.1427f, 1.2046f},
    {2.8366f, -3.0525f, 1.2012f}};

extern "C" void kernel_launch(void* const* d_in, const int* in_sizes, int n_in,
                              void* d_out, int out_size) {
    const float* w0  = (const float*)d_in[0];
    const float* w1  = (const float*)d_in[1];
    const float* w2  = (const float*)d_in[2];
    const float* q   = (const float*)d_in[3];
    const float* kin = (const float*)d_in[4];
    const float* v   = (const float*)d_in[5];
    const float* lr0 = (const float*)d_in[6];
    const float* lr1 = (const float*)d_in[7];
    const float* lr2 = (const float*)d_in[8];
    const float* mom = (const float*)d_in[9];
    const float* mlt = (const float*)d_in[10];
    float* out = (float*)d_out;

    static int smset = 0;
    if (!smset) {
        cudaFuncSetAttribute(tgemm, cudaFuncAttributeMaxDynamicSharedMemorySize, SMEM_TOTAL);
        smset = 1;
    }

    float* F;
    bf* H;
    cudaGetSymbolAddress((void**)&F, g_f);
    cudaGetSymbolAddress((void**)&H, g_h);

    k_init<<<NMAT * 512, 128>>>(w0, w1, w2);
    ts(F + F_WC + 8L * MSZ, MSZ, 512, 512, 0, 0, 0, H + H_W1TH, H + H_W1TL, MSZ, 8);

    for (int ci = 0; ci < NCHUNK; ci++) {
        int cb = ci * CS;

        // all pre-GEMM elementwise: one launch
        k_pre<<<dim3(769, 1, 8), 256>>>(kin, q, v, lr0, lr2, mom, mlt, cb);

        // activation GEMMs: 5 groups of 8 -> one launch (full tiles)
        {
            TArgs g;
            setgd(g.gd[0], H + H_WCH, H + H_WCL, MSZ, H + H_KH, H + H_KL, CHB,
                  F + F_GBA, 0, 0, 0, CHB, 0, 0, 0, 0, 0,
                  512, 256, 512, CS, 1, 1, 1.f, 0.f, 0);
            setgd(g.gd[1], H + H_WCH + 16L * MSZ, H + H_WCL + 16L * MSZ, MSZ,
                  H + H_KH, H + H_KL, CHB, F + F_HBM, 0, 0, 0, CHB, 0, 0, 0, 0, 0,
                  512, 256, 512, CS, 1, 1, 1.f, 0.f, 0);
            setgd(g.gd[2], H + H_WCH + 16L * MSZ, H + H_WCL + 16L * MSZ, MSZ,
                  H + H_QH, H + H_QL, CHB, F + F_HH, 0, 0, 0, CHB, 0, 0, 0, 0, 0,
                  512, 256, 512, CS, 1, 1, 1.f, 0.f, 0);
            setgd(g.gd[3], H + H_WCH, H + H_WCL, MSZ, H + H_QH, H + H_QL, CHB,
                  F + F_G0, 0, 0, 0, CHB, 0, 0, 0, 0, 0,
                  512, 256, 512, CS, 1, 1, 1.f, 0.f, 0);
            setgd(g.gd[4], H + H_W1TH, H + H_W1TL, MSZ, H + H_VH, H + H_VL, CHB,
                  F + F_DHID, 0, 0, 0, CHB, 0, 0, 0, 0, 0,
                  512, 256, 512, CS, 1, 1, 1.f, 0.f, 0);
            tgemm<<<dim3(2, 4, 40), 256, SMEM_TOTAL>>>(g);
        }

        k_ew12T<<<dim3(8, 16, 8), dim3(32, 8)>>>(lr1, cb);

        // merged: out GEMM + dw GEMMs (dm = dw + dm*mi fused, sumsq partials)
        {
            TArgs g;
            setgd(g.gd[0], H + H_WCH + 8L * MSZ, H + H_WCL + 8L * MSZ, MSZ,
                  H + H_GTH, H + H_GTL, CHB,
                  out + (long)cb * DD, 0, 0, 0, TDSl, 0, 0, 0, 0, 0,
                  512, 256, 512, 1, DD, 1, 1.f, 0.f, 0);
            setgd(g.gd[1], H + H_DGH, H + H_DGL, CHB, H + H_K0H, H + H_K0L, CHB,
                  F + F_DM, F + F_DM, 0, 0, MSZ, 0, 0, 0, 0, 0,
                  512, 512, 256, 512, 1, 1 | 2 | 32, 1.f, 0.f, F + F_MI);
            setgd(g.gd[2], H + H_VTH, H + H_VTL, CHB, H + H_HLH, H + H_HLL, CHB,
                  F + F_DM + 8L * MSZ, F + F_DM + 8L * MSZ, 0, 0, MSZ, 0, 0, 0, 0, 0,
                  512, 512, 256, 512, 1, 1 | 2 | 32, 1.f, 0.f, F + F_MI);
            setgd(g.gd[3], H + H_DBH, H + H_DBL, CHB, H + H_K2H, H + H_K2L, CHB,
                  F + F_DM + 16L * MSZ, F + F_DM + 16L * MSZ, 0, 0, MSZ, 0, 0, 0, 0, 0,
                  512, 512, 256, 512, 1, 1 | 2 | 32, 1.f, 0.f, F + F_MI);
            tgemm<<<dim3(4, 4, 32), 256, SMEM_TOTAL>>>(g);
        }

        k_xsplit<<<dim3(16, 16, 24), dim3(32, 8)>>>();

        // Newton-Schulz (5 iters); X and XT planes ping-pong
        for (int it = 0; it < 5; it++) {
            float aa = NSC[it][0], bb = NSC[it][1], cc = NSC[it][2];
            long xA_h  = (it & 1) ? H_X2H : H_XH;
            long xA_l  = (it & 1) ? H_X2L : H_XL;
            long xB_h  = (it & 1) ? H_XH : H_X2H;
            long xB_l  = (it & 1) ? H_XL : H_X2L;
            long xtA_h = (it & 1) ? H_XT2H : H_XTH;
            long xtA_l = (it & 1) ? H_XT2L : H_XTL;
            long xtB_h = (it & 1) ? H_XTH : H_XT2H;
            long xtB_l = (it & 1) ? H_XTL : H_XT2L;
            // A = X @ X^T : symmetric triangle, planes only
            {
                TArgs g;
                for (int j = 0; j < 3; j++) {
                    long mb = (long)j * 8 * MSZ;
                    setgd(g.gd[j], H + xA_h + mb, H + xA_l + mb, MSZ,
                          H + xA_h + mb, H + xA_l + mb, MSZ,
                          0, 0, 0, 0, MSZ,
                          H + H_AH + mb, H + H_AL + mb, 0, 0, MSZ,
                          512, 512, 512, 512, 1, 4 | 16, 1.f, 0.f, 0);
                }
                tgemm<<<dim3(10, 1, 24), 256, SMEM_TOTAL>>>(g);
            }
            // B = b*A + c*(A@A) : symmetric triangle, beta from A planes
            {
                TArgs g;
                for (int j = 0; j < 3; j++) {
                    long mb = (long)j * 8 * MSZ;
                    setgd(g.gd[j], H + H_AH + mb, H + H_AL + mb, MSZ,
                          H + H_AH + mb, H + H_AL + mb, MSZ,
                          0, 0, H + H_AH + mb, H + H_AL + mb, MSZ,
                          H + H_BH + mb, H + H_BL + mb, 0, 0, MSZ,
                          512, 512, 512, 512, 1, 4 | 16 | 64, cc, bb, 0);
                }
                tgemm<<<dim3(10, 1, 24), 256, SMEM_TOTAL>>>(g);
            }
            // X' = a*X + B@X : Dm from X[p] planes; writes X[1-p] + XT[1-p]
            {
                TArgs g;
                for (int j = 0; j < 3; j++) {
                    long mb = (long)j * 8 * MSZ;
                    setgd(g.gd[j], H + H_BH + mb, H + H_BL + mb, MSZ,
                          H + xtA_h + mb, H + xtA_l + mb, MSZ,
                          0, 0, H + xA_h + mb, H + xA_l + mb, MSZ,
                          H + xB_h + mb, H + xB_l + mb,
                          H + xtB_h + mb, H + xtB_l + mb, MSZ,
                          512, 512, 512, 512, 1, 4 | 8 | 64, 1.f, aa, 0);
                }
                tgemm<<<dim3(4, 4, 24), 256, SMEM_TOTAL>>>(g);
            }
        }

        // after 5 iters the final X lives in pair 1 (X2 planes)
        k_wupd<<<NMAT * 512, 128>>>(H + H_X2H, H + H_X2L);
        ts(F + F_WC + 8L * MSZ, MSZ, 512, 512, 0, 0, 0, H + H_W1TH, H + H_W1TL, MSZ, 8);
    }

    // final forward-only chunk
    {
        int cb = NCHUNK * CS;
        k_splitKQ<<<(int)(CHT / 256), 256>>>(kin, q, cb);
        {
            TArgs g;
            setgd(g.gd[0], H + H_WCH + 16L * MSZ, H + H_WCL + 16L * MSZ, MSZ,
                  H + H_QH, H + H_QL, CHB, F + F_HH, 0, 0, 0, CHB, 0, 0, 0, 0, 0,
                  512, 256, 512, CS, 1, 1, 1.f, 0.f, 0);
            setgd(g.gd[1], H + H_WCH, H + H_WCL, MSZ, H + H_QH, H + H_QL, CHB,
                  F + F_G0, 0, 0, 0, CHB, 0, 0, 0, 0, 0,
                  512, 256, 512, CS, 1, 1, 1.f, 0.f, 0);
            tgemm<<<dim3(2, 4, 16), 256, SMEM_TOTAL>>>(g);
        }
        k_ewfwdT<<<dim3(8, 16, 8), dim3(32, 8)>>>(cb);
        {
            TArgs g;
            setgd(g.gd[0], H + H_WCH + 8L * MSZ, H + H_WCL + 8L * MSZ, MSZ,
                  H + H_GTH, H + H_GTL, CHB,
                  out + (long)cb * DD, 0, 0, 0, TDSl, 0, 0, 0, 0, 0,
                  512, 256, 512, 1, DD, 1, 1.f, 0.f, 0);
            tgemm<<<dim3(2, 4, 8), 256, SMEM_TOTAL>>>(g);
        }
    }
}

// round 15
// speedup vs baseline: 1.1194x; 1.0776x over previous
#include <cuda_runtime.h>
#include <cuda_bf16.h>
#include <math.h>
#include <stdint.h>

// ---------------------------------------------------------------------------
// LaCT SWIGLU fast-weight attention — mma.sync bf16-split-3 GEMM engine v3.5.
// v3.4 + compact XOR-swizzled smem (64B rows, no padding): stage 40KB->32KB,
// enabling a 3-stage cp.async pipeline at occupancy 2 with ONE __syncthreads
// per K-slab (was two). ldmatrix phases verified bank-conflict-free under
// chunk' = chunk ^ ((row>>1)&3).
// ---------------------------------------------------------------------------

#define BH 8
#define TT 4096
#define DD 512
#define DI 512
#define CS 256
#define NCHUNK 15
#define NMAT 24
#define MSZ (512 * 512)
#define PLANE_B 8192                      // 128 rows x 64 bytes
#define STAGE_B (4 * PLANE_B)             // 32768
#define NSTAGE 3
#define SMEM_TOTAL (NSTAGE * STAGE_B)     // 98304 bytes

static constexpr long NM_  = (long)NMAT * MSZ;
static constexpr long W1M_ = 8L * MSZ;
static constexpr long CHB  = (long)CS * DD;
static constexpr long CHT  = (long)BH * CHB;
static constexpr long TDSl = (long)TT * DD;

// fp32 heap
static constexpr long F_WM = 0, F_WC = NM_, F_DM = 2 * NM_;
static constexpr long F_GBA = 3 * NM_, F_HBM = F_GBA + CHT, F_HH = F_HBM + CHT,
                      F_G0 = F_HH + CHT, F_DHID = F_G0 + CHT;
static constexpr long F_WNORM = F_DHID + CHT, F_MI = F_WNORM + NMAT * 512L,
                      F_MLI = F_MI + 8, F_RNS = F_MLI + 8,
                      F_RSP = F_RNS + NMAT, F_TOT = F_RSP + 512;
__device__ __align__(256) float g_f[F_TOT];

// bf16 heap
static constexpr long H_WCH = 0, H_WCL = NM_,
                      H_W1TH = 2 * NM_, H_W1TL = H_W1TH + W1M_,
                      H_XH = H_W1TL + W1M_, H_XL = H_XH + NM_,
                      H_X2H = H_XL + NM_, H_X2L = H_X2H + NM_,
                      H_XTH = H_X2L + NM_, H_XTL = H_XTH + NM_,
                      H_XT2H = H_XTL + NM_, H_XT2L = H_XT2H + NM_,
                      H_AH = H_XT2L + NM_, H_AL = H_AH + NM_,
                      H_BH = H_AL + NM_, H_BL = H_BH + NM_;
static constexpr long H_KH = H_BL + NM_, H_KL = H_KH + CHT, H_QH = H_KL + CHT,
                      H_QL = H_QH + CHT, H_VH = H_QL + CHT, H_VL = H_VH + CHT,
                      H_VTH = H_VL + CHT, H_VTL = H_VTH + CHT,
                      H_K0H = H_VTL + CHT, H_K0L = H_K0H + CHT,
                      H_K2H = H_K0L + CHT, H_K2L = H_K2H + CHT,
                      H_GTH = H_K2L + CHT, H_GTL = H_GTH + CHT,
                      H_HLH = H_GTL + CHT, H_HLL = H_HLH + CHT,
                      H_DGH = H_HLL + CHT, H_DGL = H_DGH + CHT,
                      H_DBH = H_DGL + CHT, H_DBL = H_DBH + CHT,
                      H_TOT = H_DBL + CHT;
__device__ __align__(256) __nv_bfloat16 g_h[H_TOT];

typedef __nv_bfloat16 bf;

// ------------------------- helpers -----------------------------------------
__device__ __forceinline__ uint32_t smem_u32(const void* p) {
    uint32_t a;
    asm("{ .reg .u64 t; cvta.to.shared.u64 t, %1; cvt.u32.u64 %0, t; }" : "=r"(a) : "l"(p));
    return a;
}
__device__ __forceinline__ void cp16(uint32_t dst, const void* src) {
    asm volatile("cp.async.cg.shared.global [%0], [%1], 16;" :: "r"(dst), "l"(src));
}
__device__ __forceinline__ void cp_commit() {
    asm volatile("cp.async.commit_group;" ::: "memory");
}
template <int N>
__device__ __forceinline__ void cp_wait() {
    asm volatile("cp.async.wait_group %0;" :: "n"(N) : "memory");
}
__device__ __forceinline__ void ldm4(uint32_t* f, uint32_t addr) {
    asm volatile("ldmatrix.sync.aligned.m8n8.x4.shared.b16 {%0,%1,%2,%3}, [%4];"
                 : "=r"(f[0]), "=r"(f[1]), "=r"(f[2]), "=r"(f[3]) : "r"(addr));
}
__device__ __forceinline__ void mma16816(float* c, const uint32_t* a, const uint32_t* b) {
    asm volatile("mma.sync.aligned.m16n8k16.row.col.f32.bf16.bf16.f32 "
                 "{%0,%1,%2,%3}, {%4,%5,%6,%7}, {%8,%9}, {%0,%1,%2,%3};"
                 : "+f"(c[0]), "+f"(c[1]), "+f"(c[2]), "+f"(c[3])
                 : "r"(a[0]), "r"(a[1]), "r"(a[2]), "r"(a[3]), "r"(b[0]), "r"(b[1]));
}
__device__ __forceinline__ void wsplit(bf* H, bf* L, long i, float v) {
    bf h = __float2bfloat16(v);
    H[i] = h;
    L[i] = __float2bfloat16(v - __bfloat162float(h));
}
__device__ __forceinline__ float sigf(float x) { return 1.f / (1.f + expf(-x)); }

// swizzled byte offset within a plane: row in [0,128), kh in halves {0,8,16,24}
__device__ __forceinline__ uint32_t swzoff(int row, int kh) {
    uint32_t chunk = (uint32_t)(kh >> 3);
    return (uint32_t)row * 64u + ((chunk ^ (((uint32_t)row >> 1) & 3u)) << 4);
}

// ------------------------- GEMM kernel --------------------------------------
// flags: 1=hasC, 2=Dm fp32, 4=hasO, 8=hasOT, 16=sym, 32=redsq, 64=Dm planes
struct GD {
    const bf *Ah, *Al, *Bh, *Bl;
    float* C;
    const float* Dm;
    const bf *DmH, *DmL;
    bf *OH, *OL, *OTH, *OTL;
    const float* betap;
    long As, Bs, Cs, Os;
    int M, N, K, csr, csc, flags;
    float alpha, beta;
};
struct TArgs {
    GD gd[5];
};

__device__ __forceinline__ void ldplane(uint32_t smbase, const bf* g,
                                        int r0, int Kd, int kt, int tid) {
#pragma unroll
    for (int i = 0; i < 2; i++) {
        int idx = tid + i * 256;
        int row = idx >> 2;
        int ch = (idx & 3) << 3;                  // half offset 0/8/16/24
        const bf* src = g + (long)(r0 + row) * Kd + kt + ch;
        cp16(smbase + swzoff(row, ch), src);
    }
}

__global__ __launch_bounds__(256, 2) void tgemm(const __grid_constant__ TArgs g) {
    extern __shared__ bf smh[];
    uint32_t smb = smem_u32(smh);

    const int tid = threadIdx.x;
    const int lane = tid & 31;
    const int wid = tid >> 5;
    const int wm = wid >> 2;
    const int wn = wid & 3;
    const int z = blockIdx.z;
    const GD& d = g.gd[z >> 3];
    const long zb = z & 7;
    const int flags = d.flags;

    int row0, col0, bi = 0, bj = 0;
    if (flags & 16) {
        int t = blockIdx.x;
        int i = 0;
        while (t >= (i + 1) * (i + 2) / 2) i++;
        bi = i; bj = t - i * (i + 1) / 2;
        row0 = bi * 128; col0 = bj * 128;
    } else {
        row0 = blockIdx.y * 128; col0 = blockIdx.x * 128;
        if (row0 >= d.M || col0 >= d.N) return;
    }

    const bf* Ah = d.Ah + zb * d.As;
    const bf* Al = d.Al + zb * d.As;
    const bf* Bh = d.Bh + zb * d.Bs;
    const bf* Bl = d.Bl + zb * d.Bs;
    const int Kd = d.K;
    const int nslab = Kd >> 5;

    float acc[4][4][4];
#pragma unroll
    for (int i = 0; i < 4; i++)
#pragma unroll
        for (int j = 0; j < 4; j++)
#pragma unroll
            for (int r = 0; r < 4; r++) acc[i][j][r] = 0.f;

    const int lrow = lane & 15;
    const int lcol = (lane >> 4) << 3;

    // prologue: stages 0 and 1
    {
        ldplane(smb,               Ah, row0, Kd, 0, tid);
        ldplane(smb + PLANE_B,     Al, row0, Kd, 0, tid);
        ldplane(smb + 2 * PLANE_B, Bh, col0, Kd, 0, tid);
        ldplane(smb + 3 * PLANE_B, Bl, col0, Kd, 0, tid);
        cp_commit();
        uint32_t sb = smb + STAGE_B;
        ldplane(sb,               Ah, row0, Kd, 32, tid);
        ldplane(sb + PLANE_B,     Al, row0, Kd, 32, tid);
        ldplane(sb + 2 * PLANE_B, Bh, col0, Kd, 32, tid);
        ldplane(sb + 3 * PLANE_B, Bl, col0, Kd, 32, tid);
        cp_commit();
    }

    for (int s = 0; s < nslab; s++) {
        if (s < nslab - 1) cp_wait<1>(); else cp_wait<0>();
        __syncthreads();
        if (s + 2 < nslab) {
            uint32_t sb = smb + (uint32_t)(((s + 2) % NSTAGE) * STAGE_B);
            int kt = (s + 2) << 5;
            ldplane(sb,               Ah, row0, Kd, kt, tid);
            ldplane(sb + PLANE_B,     Al, row0, Kd, kt, tid);
            ldplane(sb + 2 * PLANE_B, Bh, col0, Kd, kt, tid);
            ldplane(sb + 3 * PLANE_B, Bl, col0, Kd, kt, tid);
            cp_commit();
        }

        uint32_t sb = smb + (uint32_t)((s % NSTAGE) * STAGE_B);
#pragma unroll
        for (int k16 = 0; k16 < 2; k16++) {
            const int kh = k16 * 16 + lcol;
            uint32_t bhf[2][4], blf[2][4];
#pragma unroll
            for (int pr = 0; pr < 2; pr++) {
                int br = wn * 32 + pr * 16 + lrow;
                uint32_t off = swzoff(br, kh);
                ldm4(bhf[pr], sb + 2 * PLANE_B + off);
                ldm4(blf[pr], sb + 3 * PLANE_B + off);
            }
#pragma unroll
            for (int mt = 0; mt < 4; mt++) {
                uint32_t ahf[4], alf[4];
                int ar = wm * 64 + mt * 16 + lrow;
                uint32_t off = swzoff(ar, kh);
                ldm4(ahf, sb + off);
                ldm4(alf, sb + PLANE_B + off);
#pragma unroll
                for (int nt = 0; nt < 4; nt++) {
                    int pr = nt >> 1, hi = nt & 1;
                    uint32_t bh2[2] = {bhf[pr][hi], bhf[pr][hi + 2]};
                    uint32_t bl2[2] = {blf[pr][hi], blf[pr][hi + 2]};
                    mma16816(acc[mt][nt], ahf, bh2);
                    mma16816(acc[mt][nt], ahf, bl2);
                    mma16816(acc[mt][nt], alf, bh2);
                }
            }
        }
    }
    __syncthreads();   // smem reuse safety (tsb / rs staging below)

    // epilogue
    float* tsb = (float*)smh;
    float* C = d.C + zb * d.Cs;
    const float* Dm = d.Dm + zb * d.Cs;
    const bf* DmH = d.DmH + zb * d.Cs;
    const bf* DmL = d.DmL + zb * d.Cs;
    bf* oh = d.OH + zb * d.Os;
    bf* ol = d.OL + zb * d.Os;
    const float bcoef = d.betap ? d.betap[zb] : d.beta;
    const int gr = lane >> 2, gc = (lane & 3) * 2;
    const int domirror = (flags & 16) && (bi != bj);
    float ssq = 0.f;
#pragma unroll
    for (int mt = 0; mt < 4; mt++) {
#pragma unroll
        for (int nt = 0; nt < 4; nt++) {
#pragma unroll
            for (int rg = 0; rg < 4; rg++) {
                int rl = wm * 64 + mt * 16 + gr + ((rg >> 1) << 3);
                int cl = wn * 32 + nt * 8 + gc + (rg & 1);
                int r = row0 + rl, c = col0 + cl;
                long off = (long)r * d.csr + (long)c * d.csc;
                float val = d.alpha * acc[mt][nt][rg];
                if (flags & 2) val += bcoef * Dm[off];
                if (flags & 64)
                    val += bcoef * (__bfloat162float(DmH[off]) + __bfloat162float(DmL[off]));
                if (flags & 1) C[off] = val;
                if (flags & 32) ssq += val * val;
                bf vh = __float2bfloat16(val);
                bf vl = __float2bfloat16(val - __bfloat162float(vh));
                if (flags & 4) { oh[off] = vh; ol[off] = vl; }
                if (domirror) {
                    long offm = (long)c * d.csr + (long)r * d.csc;
                    if (flags & 1) C[offm] = val;
                    if (flags & 4) { oh[offm] = vh; ol[offm] = vl; }
                }
                if (flags & 8) tsb[rl * 129 + cl] = val;
            }
        }
    }
    if (flags & 32) {
#pragma unroll
        for (int o = 16; o > 0; o >>= 1) ssq += __shfl_xor_sync(0xffffffffu, ssq, o);
        float* rs = (float*)smh;
        if (lane == 0) rs[wid] = ssq;
        __syncthreads();
        if (tid == 0) {
            float tot = 0.f;
#pragma unroll
            for (int w = 0; w < 8; w++) tot += rs[w];
            g_f[F_RSP + (long)z * 16 + blockIdx.y * 4 + blockIdx.x] = tot;
        }
    }
    if (flags & 8) {
        __syncthreads();
        bf* oth = d.OTH + zb * d.Os;
        bf* otl = d.OTL + zb * d.Os;
#pragma unroll 4
        for (int i = 0; i < 64; i++) {
            int idx = tid + i * 256;
            int cl = idx >> 7;
            int rl = idx & 127;
            float v = tsb[rl * 129 + cl];
            long off = (long)(col0 + cl) * 512 + row0 + rl;
            bf h = __float2bfloat16(v);
            oth[off] = h;
            otl[off] = __float2bfloat16(v - __bfloat162float(h));
        }
    }
}

// ------------------------- transpose/split (fp32 src -> planes) -------------
struct TSArgs {
    const float* src; long sbs; int srows, scols;
    bf *pH, *pL; long pbs;
    bf *tH, *tL; long tbs;
};
__global__ void k_tsplit(const __grid_constant__ TSArgs a) {
    __shared__ float tile[32][33];
    int z = blockIdx.z;
    const float* S = a.src + (long)z * a.sbs;
    int c0 = blockIdx.x * 32, r0 = blockIdx.y * 32;
    int tx = threadIdx.x, ty = threadIdx.y;
#pragma unroll
    for (int j = 0; j < 4; j++) {
        int r = r0 + ty + j * 8;
        float v = S[(long)r * a.scols + c0 + tx];
        tile[ty + j * 8][tx] = v;
        if (a.pH) {
            long o = (long)z * a.pbs + (long)r * a.scols + c0 + tx;
            wsplit(a.pH, a.pL, o, v);
        }
    }
    __syncthreads();
    if (a.tH) {
#pragma unroll
        for (int j = 0; j < 4; j++) {
            int c = c0 + ty + j * 8;
            float v = tile[tx][ty + j * 8];
            long o = (long)z * a.tbs + (long)c * a.srows + r0 + tx;
            wsplit(a.tH, a.tL, o, v);
        }
    }
}

// ------------------------- elementwise/fused kernels ------------------------
__global__ void k_init(const float* w0, const float* w1, const float* w2) {
    int row = blockIdx.x;
    int m = row >> 9, w = m >> 3, bh = m & 7, r = row & 511;
    const float* src = (w == 0 ? w0 : (w == 1 ? w1 : w2)) + (long)bh * MSZ + (long)r * 512;
    long mo = (long)m * MSZ + (long)r * 512;
    int t = threadIdx.x;
    float ss = 0.f;
#pragma unroll
    for (int j = 0; j < 4; j++) {
        int c = t + j * 128;
        float v = src[c];
        g_f[F_WM + mo + c] = v;
        g_f[F_WC + mo + c] = v;
        g_f[F_DM + mo + c] = 0.f;
        wsplit(g_h + H_WCH, g_h + H_WCL, mo + c, v);
        ss += v * v;
    }
    __shared__ float red[128];
    red[t] = ss; __syncthreads();
    for (int s = 64; s > 0; s >>= 1) { if (t < s) red[t] += red[t + s]; __syncthreads(); }
    if (t == 0) g_f[F_WNORM + (long)m * 512 + r] = sqrtf(red[0]);
}

// one launch: splitKQ (512 blk/bh) + V split/T (128) + k*lr planes (128) + scalars (1)
__global__ void k_pre(const float* kin, const float* q, const float* v,
                      const float* lr0, const float* lr2,
                      const float* mom, const float* mlt, int cbase) {
    __shared__ float tile[32][33];
    int bh = blockIdx.z;
    int b = blockIdx.x;
    int tid = threadIdx.x;
    if (b < 512) {
        long idx = ((long)bh << 17) + b * 256L + tid;
        int dd = idx & 511;
        int t = (int)((idx >> 9) & 255);
        long so = (long)bh * TDSl + (long)(cbase + t) * DD + dd;
        wsplit(g_h + H_KH, g_h + H_KL, idx, kin[so]);
        wsplit(g_h + H_QH, g_h + H_QL, idx, q[so]);
        return;
    }
    int tx = tid & 31, ty = tid >> 5;
    if (b < 640) {
        int bb = b - 512;
        int c0 = (bb & 15) * 32, r0 = (bb >> 4) * 32;
        const float* S = v + (long)bh * TDSl + (long)cbase * DD;
#pragma unroll
        for (int j = 0; j < 4; j++) {
            int r = r0 + ty + j * 8;
            float val = S[(long)r * DD + c0 + tx];
            tile[ty + j * 8][tx] = val;
            long o = (long)bh * CHB + (long)r * DD + c0 + tx;
            wsplit(g_h + H_VH, g_h + H_VL, o, val);
        }
        __syncthreads();
#pragma unroll
        for (int j = 0; j < 4; j++) {
            int c = c0 + ty + j * 8;
            float val = tile[tx][ty + j * 8];
            long o = (long)bh * CHB + (long)c * CS + r0 + tx;
            wsplit(g_h + H_VTH, g_h + H_VTL, o, val);
        }
        return;
    }
    if (b < 768) {
        int bb = b - 640;
        int t0 = (bb & 7) * 32, d0 = (bb >> 3) * 32;
#pragma unroll
        for (int j = 0; j < 4; j++)
            tile[ty + 8 * j][tx] =
                kin[(long)bh * TDSl + (long)(cbase + t0 + ty + 8 * j) * DD + d0 + tx];
        __syncthreads();
        float l0 = lr0[(long)bh * TT + cbase + t0 + tx];
        float l2 = lr2[(long)bh * TT + cbase + t0 + tx];
#pragma unroll
        for (int j = 0; j < 4; j++) {
            long o = (long)bh * CHB + (long)(d0 + ty + 8 * j) * CS + t0 + tx;
            float kv = tile[tx][ty + 8 * j];
            wsplit(g_h + H_K0H, g_h + H_K0L, o, kv * l0);
            wsplit(g_h + H_K2H, g_h + H_K2L, o, kv * l2);
        }
        return;
    }
    {
        __shared__ float r1[256], r2[256];
        r1[tid] = mom[(long)bh * TT + cbase + tid];
        r2[tid] = mlt[(long)bh * TT + cbase + tid];
        __syncthreads();
        for (int s = 128; s > 0; s >>= 1) {
            if (tid < s) { r1[tid] += r1[tid + s]; r2[tid] += r2[tid + s]; }
            __syncthreads();
        }
        if (tid == 0) {
            g_f[F_MI + bh] = r1[0] * (1.f / CS);
            g_f[F_MLI + bh] = r2[0] * (1.f / CS);
        }
    }
}

__global__ void k_splitKQ(const float* kin, const float* q, int cbase) {
    long idx = blockIdx.x * 256L + threadIdx.x;
    int dd = idx & 511;
    int t = (int)((idx >> 9) & 255);
    int bh = (int)(idx >> 17);
    long so = (long)bh * TDSl + (long)(cbase + t) * DD + dd;
    wsplit(g_h + H_KH, g_h + H_KL, idx, kin[so]);
    wsplit(g_h + H_QH, g_h + H_QL, idx, q[so]);
}

__global__ void k_ew12T(const float* lr1, int cbase) {
    __shared__ float tile[32][33];
    int bh = blockIdx.z;
    int t0 = blockIdx.x * 32, di0 = blockIdx.y * 32;
    int tx = threadIdx.x, ty = threadIdx.y;
    float l1 = lr1[(long)bh * TT + cbase + t0 + tx];
#pragma unroll
    for (int j = 0; j < 4; j++) {
        long idx = (long)bh * CHB + (long)(di0 + ty + 8 * j) * CS + t0 + tx;
        float gba = g_f[F_GBA + idx], hbm = g_f[F_HBM + idx], dh = g_f[F_DHID + idx];
        float sg = sigf(gba), sil = gba * sg;
        wsplit(g_h + H_HLH, g_h + H_HLL, idx, sil * hbm * l1);
        wsplit(g_h + H_DBH, g_h + H_DBL, idx, dh * sil);
        float dgate = dh * hbm;
        wsplit(g_h + H_DGH, g_h + H_DGL, idx, dgate * sg * (1.f + gba * (1.f - sg)));
        float g0v = g_f[F_G0 + idx], hv = g_f[F_HH + idx];
        tile[ty + 8 * j][tx] = g0v * sigf(g0v) * hv;
    }
    __syncthreads();
#pragma unroll
    for (int j = 0; j < 4; j++) {
        long o = (long)bh * CHB + (long)(t0 + ty + 8 * j) * DI + di0 + tx;
        wsplit(g_h + H_GTH, g_h + H_GTL, o, tile[tx][ty + 8 * j]);
    }
}

__global__ void k_ewfwdT(int cbase) {
    __shared__ float tile[32][33];
    int bh = blockIdx.z;
    int t0 = blockIdx.x * 32, di0 = blockIdx.y * 32;
    int tx = threadIdx.x, ty = threadIdx.y;
#pragma unroll
    for (int j = 0; j < 4; j++) {
        long idx = (long)bh * CHB + (long)(di0 + ty + 8 * j) * CS + t0 + tx;
        float g0v = g_f[F_G0 + idx], hv = g_f[F_HH + idx];
        tile[ty + 8 * j][tx] = g0v * sigf(g0v) * hv;
    }
    __syncthreads();
#pragma unroll
    for (int j = 0; j < 4; j++) {
        long o = (long)bh * CHB + (long)(t0 + ty + 8 * j) * DI + di0 + tx;
        wsplit(g_h + H_GTH, g_h + H_GTL, o, tile[tx][ty + 8 * j]);
    }
}

// dm*rns -> X planes (pair 0) + XT planes (pair 0); rns computed in-block
__global__ void k_xsplit() {
    __shared__ float tile[32][33];
    __shared__ float rns_s;
    int m = blockIdx.z;
    int c0 = blockIdx.x * 32, r0 = blockIdx.y * 32;
    int tx = threadIdx.x, ty = threadIdx.y;
    if (tx == 0 && ty == 0) {
        float s = 0.f;
#pragma unroll
        for (int i = 0; i < 16; i++) s += g_f[F_RSP + (long)(m + 8) * 16 + i];
        rns_s = 1.f / (sqrtf(s) + 1e-7f);
    }
    __syncthreads();
    float rn = rns_s;
#pragma unroll
    for (int j = 0; j < 4; j++) {
        long i = (long)m * MSZ + (long)(r0 + ty + 8 * j) * 512 + c0 + tx;
        float v = g_f[F_DM + i] * rn;
        wsplit(g_h + H_XH, g_h + H_XL, i, v);
        tile[ty + 8 * j][tx] = v;
    }
    __syncthreads();
#pragma unroll
    for (int j = 0; j < 4; j++) {
        long o = (long)m * MSZ + (long)(c0 + ty + 8 * j) * 512 + r0 + tx;
        wsplit(g_h + H_XTH, g_h + H_XTL, o, tile[tx][ty + 8 * j]);
    }
}

__global__ void k_wupd(const bf* xh, const bf* xl) {
    int row = blockIdx.x;
    int m = row >> 9, bh = m & 7, r = row & 511;
    long mo = (long)m * MSZ + (long)r * 512;
    float ml = g_f[F_MLI + bh];
    int t = threadIdx.x;
    float vals[4];
    float ss = 0.f;
#pragma unroll
    for (int j = 0; j < 4; j++) {
        int c = t + j * 128;
        float xv = __bfloat162float(xh[mo + c]) + __bfloat162float(xl[mo + c]);
        float v = g_f[F_WM + mo + c] + xv * ml;
        g_f[F_WM + mo + c] = v;
        vals[j] = v;
        ss += v * v;
    }
    __shared__ float red[128];
    red[t] = ss; __syncthreads();
    for (int s = 64; s > 0; s >>= 1) { if (t < s) red[t] += red[t + s]; __syncthreads(); }
    float scale = g_f[F_WNORM + (long)m * 512 + r] / (sqrtf(red[0]) + 1e-5f);
#pragma unroll
    for (int j = 0; j < 4; j++) {
        int c = t + j * 128;
        float w = vals[j] * scale;
        g_f[F_WC + mo + c] = w;
        wsplit(g_h + H_WCH, g_h + H_WCL, mo + c, w);
    }
}

// ------------------------- host orchestration -------------------------------
static void setgd(GD& d, const bf* Ah, const bf* Al, long As,
                  const bf* Bh, const bf* Bl, long Bs,
                  float* C, const float* Dm, const bf* DmH, const bf* DmL, long Cs,
                  bf* OH, bf* OL, bf* OTH, bf* OTL, long Os,
                  int M, int N, int K, int csr, int csc, int flags,
                  float alpha, float beta, const float* betap) {
    d.Ah = Ah; d.Al = Al; d.Bh = Bh; d.Bl = Bl;
    d.C = C; d.Dm = Dm; d.DmH = DmH; d.DmL = DmL;
    d.OH = OH; d.OL = OL; d.OTH = OTH; d.OTL = OTL;
    d.betap = betap;
    d.As = As; d.Bs = Bs; d.Cs = Cs; d.Os = Os;
    d.M = M; d.N = N; d.K = K; d.csr = csr; d.csc = csc; d.flags = flags;
    d.alpha = alpha; d.beta = beta;
}

static void ts(const float* src, long sbs, int srows, int scols,
               bf* pH, bf* pL, long pbs, bf* tH, bf* tL, long tbs, int batch) {
    TSArgs a;
    a.src = src; a.sbs = sbs; a.srows = srows; a.scols = scols;
    a.pH = pH; a.pL = pL; a.pbs = pbs;
    a.tH = tH; a.tL = tL; a.tbs = tbs;
    k_tsplit<<<dim3(scols / 32, srows / 32, batch), dim3(32, 8)>>>(a);
}

static const float NSC[5][3] = {
    {4.0848f, -6.8946f, 2.927f},
    {3.9505f, -6.3029f, 2.6377f},
    {3.7418f, -5.5913f, 2.3037f},
    {2.8769f, -3.1427f, 1.2046f},
    {2.8366f, -3.0525f, 1.2012f}};

extern "C" void kernel_launch(void* const* d_in, const int* in_sizes, int n_in,
                              void* d_out, int out_size) {
    const float* w0  = (const float*)d_in[0];
    const float* w1  = (const float*)d_in[1];
    const float* w2  = (const float*)d_in[2];
    const float* q   = (const float*)d_in[3];
    const float* kin = (const float*)d_in[4];
    const float* v   = (const float*)d_in[5];
    const float* lr0 = (const float*)d_in[6];
    const float* lr1 = (const float*)d_in[7];
    const float* lr2 = (const float*)d_in[8];
    const float* mom = (const float*)d_in[9];
    const float* mlt = (const float*)d_in[10];
    float* out = (float*)d_out;

    static int smset = 0;
    if (!smset) {
        cudaFuncSetAttribute(tgemm, cudaFuncAttributeMaxDynamicSharedMemorySize, SMEM_TOTAL);
        smset = 1;
    }

    float* F;
    bf* H;
    cudaGetSymbolAddress((void**)&F, g_f);
    cudaGetSymbolAddress((void**)&H, g_h);

    k_init<<<NMAT * 512, 128>>>(w0, w1, w2);
    ts(F + F_WC + 8L * MSZ, MSZ, 512, 512, 0, 0, 0, H + H_W1TH, H + H_W1TL, MSZ, 8);

    for (int ci = 0; ci < NCHUNK; ci++) {
        int cb = ci * CS;

        k_pre<<<dim3(769, 1, 8), 256>>>(kin, q, v, lr0, lr2, mom, mlt, cb);

        // activation GEMMs: 5 groups of 8 -> one launch
        {
            TArgs g;
            setgd(g.gd[0], H + H_WCH, H + H_WCL, MSZ, H + H_KH, H + H_KL, CHB,
                  F + F_GBA, 0, 0, 0, CHB, 0, 0, 0, 0, 0,
                  512, 256, 512, CS, 1, 1, 1.f, 0.f, 0);
            setgd(g.gd[1], H + H_WCH + 16L * MSZ, H + H_WCL + 16L * MSZ, MSZ,
                  H + H_KH, H + H_KL, CHB, F + F_HBM, 0, 0, 0, CHB, 0, 0, 0, 0, 0,
                  512, 256, 512, CS, 1, 1, 1.f, 0.f, 0);
            setgd(g.gd[2], H + H_WCH + 16L * MSZ, H + H_WCL + 16L * MSZ, MSZ,
                  H + H_QH, H + H_QL, CHB, F + F_HH, 0, 0, 0, CHB, 0, 0, 0, 0, 0,
                  512, 256, 512, CS, 1, 1, 1.f, 0.f, 0);
            setgd(g.gd[3], H + H_WCH, H + H_WCL, MSZ, H + H_QH, H + H_QL, CHB,
                  F + F_G0, 0, 0, 0, CHB, 0, 0, 0, 0, 0,
                  512, 256, 512, CS, 1, 1, 1.f, 0.f, 0);
            setgd(g.gd[4], H + H_W1TH, H + H_W1TL, MSZ, H + H_VH, H + H_VL, CHB,
                  F + F_DHID, 0, 0, 0, CHB, 0, 0, 0, 0, 0,
                  512, 256, 512, CS, 1, 1, 1.f, 0.f, 0);
            tgemm<<<dim3(2, 4, 40), 256, SMEM_TOTAL>>>(g);
        }

        k_ew12T<<<dim3(8, 16, 8), dim3(32, 8)>>>(lr1, cb);

        // merged: out GEMM + dw GEMMs (dm = dw + dm*mi fused, sumsq partials)
        {
            TArgs g;
            setgd(g.gd[0], H + H_WCH + 8L * MSZ, H + H_WCL + 8L * MSZ, MSZ,
                  H + H_GTH, H + H_GTL, CHB,
                  out + (long)cb * DD, 0, 0, 0, TDSl, 0, 0, 0, 0, 0,
                  512, 256, 512, 1, DD, 1, 1.f, 0.f, 0);
            setgd(g.gd[1], H + H_DGH, H + H_DGL, CHB, H + H_K0H, H + H_K0L, CHB,
                  F + F_DM, F + F_DM, 0, 0, MSZ, 0, 0, 0, 0, 0,
                  512, 512, 256, 512, 1, 1 | 2 | 32, 1.f, 0.f, F + F_MI);
            setgd(g.gd[2], H + H_VTH, H + H_VTL, CHB, H + H_HLH, H + H_HLL, CHB,
                  F + F_DM + 8L * MSZ, F + F_DM + 8L * MSZ, 0, 0, MSZ, 0, 0, 0, 0, 0,
                  512, 512, 256, 512, 1, 1 | 2 | 32, 1.f, 0.f, F + F_MI);
            setgd(g.gd[3], H + H_DBH, H + H_DBL, CHB, H + H_K2H, H + H_K2L, CHB,
                  F + F_DM + 16L * MSZ, F + F_DM + 16L * MSZ, 0, 0, MSZ, 0, 0, 0, 0, 0,
                  512, 512, 256, 512, 1, 1 | 2 | 32, 1.f, 0.f, F + F_MI);
            tgemm<<<dim3(4, 4, 32), 256, SMEM_TOTAL>>>(g);
        }

        k_xsplit<<<dim3(16, 16, 24), dim3(32, 8)>>>();

        // Newton-Schulz (5 iters); X and XT planes ping-pong
        for (int it = 0; it < 5; it++) {
            float aa = NSC[it][0], bb = NSC[it][1], cc = NSC[it][2];
            long xA_h  = (it & 1) ? H_X2H : H_XH;
            long xA_l  = (it & 1) ? H_X2L : H_XL;
            long xB_h  = (it & 1) ? H_XH : H_X2H;
            long xB_l  = (it & 1) ? H_XL : H_X2L;
            long xtA_h = (it & 1) ? H_XT2H : H_XTH;
            long xtA_l = (it & 1) ? H_XT2L : H_XTL;
            long xtB_h = (it & 1) ? H_XTH : H_XT2H;
            long xtB_l = (it & 1) ? H_XTL : H_XT2L;
            // A = X @ X^T : symmetric triangle, planes only
            {
                TArgs g;
                for (int j = 0; j < 3; j++) {
                    long mb = (long)j * 8 * MSZ;
                    setgd(g.gd[j], H + xA_h + mb, H + xA_l + mb, MSZ,
                          H + xA_h + mb, H + xA_l + mb, MSZ,
                          0, 0, 0, 0, MSZ,
                          H + H_AH + mb, H + H_AL + mb, 0, 0, MSZ,
                          512, 512, 512, 512, 1, 4 | 16, 1.f, 0.f, 0);
                }
                tgemm<<<dim3(10, 1, 24), 256, SMEM_TOTAL>>>(g);
            }
            // B = b*A + c*(A@A) : symmetric triangle, beta from A planes
            {
                TArgs g;
                for (int j = 0; j < 3; j++) {
                    long mb = (long)j * 8 * MSZ;
                    setgd(g.gd[j], H + H_AH + mb, H + H_AL + mb, MSZ,
                          H + H_AH + mb, H + H_AL + mb, MSZ,
                          0, 0, H + H_AH + mb, H + H_AL + mb, MSZ,
                          H + H_BH + mb, H + H_BL + mb, 0, 0, MSZ,
                          512, 512, 512, 512, 1, 4 | 16 | 64, cc, bb, 0);
                }
                tgemm<<<dim3(10, 1, 24), 256, SMEM_TOTAL>>>(g);
            }
            // X' = a*X + B@X : Dm from X[p] planes; writes X[1-p] + XT[1-p]
            {
                TArgs g;
                for (int j = 0; j < 3; j++) {
                    long mb = (long)j * 8 * MSZ;
                    setgd(g.gd[j], H + H_BH + mb, H + H_BL + mb, MSZ,
                          H + xtA_h + mb, H + xtA_l + mb, MSZ,
                          0, 0, H + xA_h + mb, H + xA_l + mb, MSZ,
                          H + xB_h + mb, H + xB_l + mb,
                          H + xtB_h + mb, H + xtB_l + mb, MSZ,
                          512, 512, 512, 512, 1, 4 | 8 | 64, 1.f, aa, 0);
                }
                tgemm<<<dim3(4, 4, 24), 256, SMEM_TOTAL>>>(g);
            }
        }

        // after 5 iters the final X lives in pair 1 (X2 planes)
        k_wupd<<<NMAT * 512, 128>>>(H + H_X2H, H + H_X2L);
        ts(F + F_WC + 8L * MSZ, MSZ, 512, 512, 0, 0, 0, H + H_W1TH, H + H_W1TL, MSZ, 8);
    }

    // final forward-only chunk
    {
        int cb = NCHUNK * CS;
        k_splitKQ<<<(int)(CHT / 256), 256>>>(kin, q, cb);
        {
            TArgs g;
            setgd(g.gd[0], H + H_WCH + 16L * MSZ, H + H_WCL + 16L * MSZ, MSZ,
                  H + H_QH, H + H_QL, CHB, F + F_HH, 0, 0, 0, CHB, 0, 0, 0, 0, 0,
                  512, 256, 512, CS, 1, 1, 1.f, 0.f, 0);
            setgd(g.gd[1], H + H_WCH, H + H_WCL, MSZ, H + H_QH, H + H_QL, CHB,
                  F + F_G0, 0, 0, 0, CHB, 0, 0, 0, 0, 0,
                  512, 256, 512, CS, 1, 1, 1.f, 0.f, 0);
            tgemm<<<dim3(2, 4, 16), 256, SMEM_TOTAL>>>(g);
        }
        k_ewfwdT<<<dim3(8, 16, 8), dim3(32, 8)>>>(cb);
        {
            TArgs g;
            setgd(g.gd[0], H + H_WCH + 8L * MSZ, H + H_WCL + 8L * MSZ, MSZ,
                  H + H_GTH, H + H_GTL, CHB,
                  out + (long)cb * DD, 0, 0, 0, TDSl, 0, 0, 0, 0, 0,
                  512, 256, 512, 1, DD, 1, 1.f, 0.f, 0);
            tgemm<<<dim3(2, 4, 8), 256, SMEM_TOTAL>>>(g);
        }
    }
}

// round 16
// speedup vs baseline: 1.1217x; 1.0020x over previous
#include <cuda_runtime.h>
#include <cuda_bf16.h>
#include <math.h>
#include <stdint.h>

// ---------------------------------------------------------------------------
// LaCT SWIGLU fast-weight attention — mma.sync bf16-split-3 GEMM engine v3.6.
// v3.5 + term-major MMA issue order in the mainloop: the 3 split-3 MMAs per
// accumulator are spread across nt-passes (reuse distance 1 -> 4) so HMMA
// accumulator RAW latency is hidden by 4 independent chains. Per-accumulator
// order unchanged (hh->hl->lh) => bit-identical results.
// ---------------------------------------------------------------------------

#define BH 8
#define TT 4096
#define DD 512
#define DI 512
#define CS 256
#define NCHUNK 15
#define NMAT 24
#define MSZ (512 * 512)
#define PLANE_B 8192                      // 128 rows x 64 bytes
#define STAGE_B (4 * PLANE_B)             // 32768
#define NSTAGE 3
#define SMEM_TOTAL (NSTAGE * STAGE_B)     // 98304 bytes

static constexpr long NM_  = (long)NMAT * MSZ;
static constexpr long W1M_ = 8L * MSZ;
static constexpr long CHB  = (long)CS * DD;
static constexpr long CHT  = (long)BH * CHB;
static constexpr long TDSl = (long)TT * DD;

// fp32 heap
static constexpr long F_WM = 0, F_WC = NM_, F_DM = 2 * NM_;
static constexpr long F_GBA = 3 * NM_, F_HBM = F_GBA + CHT, F_HH = F_HBM + CHT,
                      F_G0 = F_HH + CHT, F_DHID = F_G0 + CHT;
static constexpr long F_WNORM = F_DHID + CHT, F_MI = F_WNORM + NMAT * 512L,
                      F_MLI = F_MI + 8, F_RNS = F_MLI + 8,
                      F_RSP = F_RNS + NMAT, F_TOT = F_RSP + 512;
__device__ __align__(256) float g_f[F_TOT];

// bf16 heap
static constexpr long H_WCH = 0, H_WCL = NM_,
                      H_W1TH = 2 * NM_, H_W1TL = H_W1TH + W1M_,
                      H_XH = H_W1TL + W1M_, H_XL = H_XH + NM_,
                      H_X2H = H_XL + NM_, H_X2L = H_X2H + NM_,
                      H_XTH = H_X2L + NM_, H_XTL = H_XTH + NM_,
                      H_XT2H = H_XTL + NM_, H_XT2L = H_XT2H + NM_,
                      H_AH = H_XT2L + NM_, H_AL = H_AH + NM_,
                      H_BH = H_AL + NM_, H_BL = H_BH + NM_;
static constexpr long H_KH = H_BL + NM_, H_KL = H_KH + CHT, H_QH = H_KL + CHT,
                      H_QL = H_QH + CHT, H_VH = H_QL + CHT, H_VL = H_VH + CHT,
                      H_VTH = H_VL + CHT, H_VTL = H_VTH + CHT,
                      H_K0H = H_VTL + CHT, H_K0L = H_K0H + CHT,
                      H_K2H = H_K0L + CHT, H_K2L = H_K2H + CHT,
                      H_GTH = H_K2L + CHT, H_GTL = H_GTH + CHT,
                      H_HLH = H_GTL + CHT, H_HLL = H_HLH + CHT,
                      H_DGH = H_HLL + CHT, H_DGL = H_DGH + CHT,
                      H_DBH = H_DGL + CHT, H_DBL = H_DBH + CHT,
                      H_TOT = H_DBL + CHT;
__device__ __align__(256) __nv_bfloat16 g_h[H_TOT];

typedef __nv_bfloat16 bf;

// ------------------------- helpers -----------------------------------------
__device__ __forceinline__ uint32_t smem_u32(const void* p) {
    uint32_t a;
    asm("{ .reg .u64 t; cvta.to.shared.u64 t, %1; cvt.u32.u64 %0, t; }" : "=r"(a) : "l"(p));
    return a;
}
__device__ __forceinline__ void cp16(uint32_t dst, const void* src) {
    asm volatile("cp.async.cg.shared.global [%0], [%1], 16;" :: "r"(dst), "l"(src));
}
__device__ __forceinline__ void cp_commit() {
    asm volatile("cp.async.commit_group;" ::: "memory");
}
template <int N>
__device__ __forceinline__ void cp_wait() {
    asm volatile("cp.async.wait_group %0;" :: "n"(N) : "memory");
}
__device__ __forceinline__ void ldm4(uint32_t* f, uint32_t addr) {
    asm volatile("ldmatrix.sync.aligned.m8n8.x4.shared.b16 {%0,%1,%2,%3}, [%4];"
                 : "=r"(f[0]), "=r"(f[1]), "=r"(f[2]), "=r"(f[3]) : "r"(addr));
}
__device__ __forceinline__ void mma16816(float* c, const uint32_t* a, const uint32_t* b) {
    asm volatile("mma.sync.aligned.m16n8k16.row.col.f32.bf16.bf16.f32 "
                 "{%0,%1,%2,%3}, {%4,%5,%6,%7}, {%8,%9}, {%0,%1,%2,%3};"
                 : "+f"(c[0]), "+f"(c[1]), "+f"(c[2]), "+f"(c[3])
                 : "r"(a[0]), "r"(a[1]), "r"(a[2]), "r"(a[3]), "r"(b[0]), "r"(b[1]));
}
__device__ __forceinline__ void wsplit(bf* H, bf* L, long i, float v) {
    bf h = __float2bfloat16(v);
    H[i] = h;
    L[i] = __float2bfloat16(v - __bfloat162float(h));
}
__device__ __forceinline__ float sigf(float x) { return 1.f / (1.f + expf(-x)); }

// swizzled byte offset within a plane: row in [0,128), kh in halves {0,8,16,24}
__device__ __forceinline__ uint32_t swzoff(int row, int kh) {
    uint32_t chunk = (uint32_t)(kh >> 3);
    return (uint32_t)row * 64u + ((chunk ^ (((uint32_t)row >> 1) & 3u)) << 4);
}

// ------------------------- GEMM kernel --------------------------------------
// flags: 1=hasC, 2=Dm fp32, 4=hasO, 8=hasOT, 16=sym, 32=redsq, 64=Dm planes
struct GD {
    const bf *Ah, *Al, *Bh, *Bl;
    float* C;
    const float* Dm;
    const bf *DmH, *DmL;
    bf *OH, *OL, *OTH, *OTL;
    const float* betap;
    long As, Bs, Cs, Os;
    int M, N, K, csr, csc, flags;
    float alpha, beta;
};
struct TArgs {
    GD gd[5];
};

__device__ __forceinline__ void ldplane(uint32_t smbase, const bf* g,
                                        int r0, int Kd, int kt, int tid) {
#pragma unroll
    for (int i = 0; i < 2; i++) {
        int idx = tid + i * 256;
        int row = idx >> 2;
        int ch = (idx & 3) << 3;
        const bf* src = g + (long)(r0 + row) * Kd + kt + ch;
        cp16(smbase + swzoff(row, ch), src);
    }
}

__global__ __launch_bounds__(256, 2) void tgemm(const __grid_constant__ TArgs g) {
    extern __shared__ bf smh[];
    uint32_t smb = smem_u32(smh);

    const int tid = threadIdx.x;
    const int lane = tid & 31;
    const int wid = tid >> 5;
    const int wm = wid >> 2;
    const int wn = wid & 3;
    const int z = blockIdx.z;
    const GD& d = g.gd[z >> 3];
    const long zb = z & 7;
    const int flags = d.flags;

    int row0, col0, bi = 0, bj = 0;
    if (flags & 16) {
        int t = blockIdx.x;
        int i = 0;
        while (t >= (i + 1) * (i + 2) / 2) i++;
        bi = i; bj = t - i * (i + 1) / 2;
        row0 = bi * 128; col0 = bj * 128;
    } else {
        row0 = blockIdx.y * 128; col0 = blockIdx.x * 128;
        if (row0 >= d.M || col0 >= d.N) return;
    }

    const bf* Ah = d.Ah + zb * d.As;
    const bf* Al = d.Al + zb * d.As;
    const bf* Bh = d.Bh + zb * d.Bs;
    const bf* Bl = d.Bl + zb * d.Bs;
    const int Kd = d.K;
    const int nslab = Kd >> 5;

    float acc[4][4][4];
#pragma unroll
    for (int i = 0; i < 4; i++)
#pragma unroll
        for (int j = 0; j < 4; j++)
#pragma unroll
            for (int r = 0; r < 4; r++) acc[i][j][r] = 0.f;

    const int lrow = lane & 15;
    const int lcol = (lane >> 4) << 3;

    // prologue: stages 0 and 1
    {
        ldplane(smb,               Ah, row0, Kd, 0, tid);
        ldplane(smb + PLANE_B,     Al, row0, Kd, 0, tid);
        ldplane(smb + 2 * PLANE_B, Bh, col0, Kd, 0, tid);
        ldplane(smb + 3 * PLANE_B, Bl, col0, Kd, 0, tid);
        cp_commit();
        uint32_t sb = smb + STAGE_B;
        ldplane(sb,               Ah, row0, Kd, 32, tid);
        ldplane(sb + PLANE_B,     Al, row0, Kd, 32, tid);
        ldplane(sb + 2 * PLANE_B, Bh, col0, Kd, 32, tid);
        ldplane(sb + 3 * PLANE_B, Bl, col0, Kd, 32, tid);
        cp_commit();
    }

    for (int s = 0; s < nslab; s++) {
        if (s < nslab - 1) cp_wait<1>(); else cp_wait<0>();
        __syncthreads();
        if (s + 2 < nslab) {
            uint32_t sb = smb + (uint32_t)(((s + 2) % NSTAGE) * STAGE_B);
            int kt = (s + 2) << 5;
            ldplane(sb,               Ah, row0, Kd, kt, tid);
            ldplane(sb + PLANE_B,     Al, row0, Kd, kt, tid);
            ldplane(sb + 2 * PLANE_B, Bh, col0, Kd, kt, tid);
            ldplane(sb + 3 * PLANE_B, Bl, col0, Kd, kt, tid);
            cp_commit();
        }

        uint32_t sb = smb + (uint32_t)((s % NSTAGE) * STAGE_B);
#pragma unroll
        for (int k16 = 0; k16 < 2; k16++) {
            const int kh = k16 * 16 + lcol;
            uint32_t bhf[2][4], blf[2][4];
#pragma unroll
            for (int pr = 0; pr < 2; pr++) {
                int br = wn * 32 + pr * 16 + lrow;
                uint32_t off = swzoff(br, kh);
                ldm4(bhf[pr], sb + 2 * PLANE_B + off);
                ldm4(blf[pr], sb + 3 * PLANE_B + off);
            }
#pragma unroll
            for (int mt = 0; mt < 4; mt++) {
                uint32_t ahf[4], alf[4];
                int ar = wm * 64 + mt * 16 + lrow;
                uint32_t off = swzoff(ar, kh);
                ldm4(ahf, sb + off);
                ldm4(alf, sb + PLANE_B + off);
                // term-major: spread same-acc MMAs to reuse distance 4
#pragma unroll
                for (int nt = 0; nt < 4; nt++) {
                    int pr = nt >> 1, hi = nt & 1;
                    uint32_t bh2[2] = {bhf[pr][hi], bhf[pr][hi + 2]};
                    mma16816(acc[mt][nt], ahf, bh2);
                }
#pragma unroll
                for (int nt = 0; nt < 4; nt++) {
                    int pr = nt >> 1, hi = nt & 1;
                    uint32_t bl2[2] = {blf[pr][hi], blf[pr][hi + 2]};
                    mma16816(acc[mt][nt], ahf, bl2);
                }
#pragma unroll
                for (int nt = 0; nt < 4; nt++) {
                    int pr = nt >> 1, hi = nt & 1;
                    uint32_t bh2[2] = {bhf[pr][hi], bhf[pr][hi + 2]};
                    mma16816(acc[mt][nt], alf, bh2);
                }
            }
        }
    }
    __syncthreads();   // smem reuse safety (tsb / rs staging below)

    // epilogue
    float* tsb = (float*)smh;
    float* C = d.C + zb * d.Cs;
    const float* Dm = d.Dm + zb * d.Cs;
    const bf* DmH = d.DmH + zb * d.Cs;
    const bf* DmL = d.DmL + zb * d.Cs;
    bf* oh = d.OH + zb * d.Os;
    bf* ol = d.OL + zb * d.Os;
    const float bcoef = d.betap ? d.betap[zb] : d.beta;
    const int gr = lane >> 2, gc = (lane & 3) * 2;
    const int domirror = (flags & 16) && (bi != bj);
    float ssq = 0.f;
#pragma unroll
    for (int mt = 0; mt < 4; mt++) {
#pragma unroll
        for (int nt = 0; nt < 4; nt++) {
#pragma unroll
            for (int rg = 0; rg < 4; rg++) {
                int rl = wm * 64 + mt * 16 + gr + ((rg >> 1) << 3);
                int cl = wn * 32 + nt * 8 + gc + (rg & 1);
                int r = row0 + rl, c = col0 + cl;
                long off = (long)r * d.csr + (long)c * d.csc;
                float val = d.alpha * acc[mt][nt][rg];
                if (flags & 2) val += bcoef * Dm[off];
                if (flags & 64)
                    val += bcoef * (__bfloat162float(DmH[off]) + __bfloat162float(DmL[off]));
                if (flags & 1) C[off] = val;
                if (flags & 32) ssq += val * val;
                bf vh = __float2bfloat16(val);
                bf vl = __float2bfloat16(val - __bfloat162float(vh));
                if (flags & 4) { oh[off] = vh; ol[off] = vl; }
                if (domirror) {
                    long offm = (long)c * d.csr + (long)r * d.csc;
                    if (flags & 1) C[offm] = val;
                    if (flags & 4) { oh[offm] = vh; ol[offm] = vl; }
                }
                if (flags & 8) tsb[rl * 129 + cl] = val;
            }
        }
    }
    if (flags & 32) {
#pragma unroll
        for (int o = 16; o > 0; o >>= 1) ssq += __shfl_xor_sync(0xffffffffu, ssq, o);
        float* rs = (float*)smh;
        if (lane == 0) rs[wid] = ssq;
        __syncthreads();
        if (tid == 0) {
            float tot = 0.f;
#pragma unroll
            for (int w = 0; w < 8; w++) tot += rs[w];
            g_f[F_RSP + (long)z * 16 + blockIdx.y * 4 + blockIdx.x] = tot;
        }
    }
    if (flags & 8) {
        __syncthreads();
        bf* oth = d.OTH + zb * d.Os;
        bf* otl = d.OTL + zb * d.Os;
#pragma unroll 4
        for (int i = 0; i < 64; i++) {
            int idx = tid + i * 256;
            int cl = idx >> 7;
            int rl = idx & 127;
            float v = tsb[rl * 129 + cl];
            long off = (long)(col0 + cl) * 512 + row0 + rl;
            bf h = __float2bfloat16(v);
            oth[off] = h;
            otl[off] = __float2bfloat16(v - __bfloat162float(h));
        }
    }
}

// ------------------------- transpose/split (fp32 src -> planes) -------------
struct TSArgs {
    const float* src; long sbs; int srows, scols;
    bf *pH, *pL; long pbs;
    bf *tH, *tL; long tbs;
};
__global__ void k_tsplit(const __grid_constant__ TSArgs a) {
    __shared__ float tile[32][33];
    int z = blockIdx.z;
    const float* S = a.src + (long)z * a.sbs;
    int c0 = blockIdx.x * 32, r0 = blockIdx.y * 32;
    int tx = threadIdx.x, ty = threadIdx.y;
#pragma unroll
    for (int j = 0; j < 4; j++) {
        int r = r0 + ty + j * 8;
        float v = S[(long)r * a.scols + c0 + tx];
        tile[ty + j * 8][tx] = v;
        if (a.pH) {
            long o = (long)z * a.pbs + (long)r * a.scols + c0 + tx;
            wsplit(a.pH, a.pL, o, v);
        }
    }
    __syncthreads();
    if (a.tH) {
#pragma unroll
        for (int j = 0; j < 4; j++) {
            int c = c0 + ty + j * 8;
            float v = tile[tx][ty + j * 8];
            long o = (long)z * a.tbs + (long)c * a.srows + r0 + tx;
            wsplit(a.tH, a.tL, o, v);
        }
    }
}

// ------------------------- elementwise/fused kernels ------------------------
__global__ void k_init(const float* w0, const float* w1, const float* w2) {
    int row = blockIdx.x;
    int m = row >> 9, w = m >> 3, bh = m & 7, r = row & 511;
    const float* src = (w == 0 ? w0 : (w == 1 ? w1 : w2)) + (long)bh * MSZ + (long)r * 512;
    long mo = (long)m * MSZ + (long)r * 512;
    int t = threadIdx.x;
    float ss = 0.f;
#pragma unroll
    for (int j = 0; j < 4; j++) {
        int c = t + j * 128;
        float v = src[c];
        g_f[F_WM + mo + c] = v;
        g_f[F_WC + mo + c] = v;
        g_f[F_DM + mo + c] = 0.f;
        wsplit(g_h + H_WCH, g_h + H_WCL, mo + c, v);
        ss += v * v;
    }
    __shared__ float red[128];
    red[t] = ss; __syncthreads();
    for (int s = 64; s > 0; s >>= 1) { if (t < s) red[t] += red[t + s]; __syncthreads(); }
    if (t == 0) g_f[F_WNORM + (long)m * 512 + r] = sqrtf(red[0]);
}

// one launch: splitKQ (512 blk/bh) + V split/T (128) + k*lr planes (128) + scalars (1)
__global__ void k_pre(const float* kin, const float* q, const float* v,
                      const float* lr0, const float* lr2,
                      const float* mom, const float* mlt, int cbase) {
    __shared__ float tile[32][33];
    int bh = blockIdx.z;
    int b = blockIdx.x;
    int tid = threadIdx.x;
    if (b < 512) {
        long idx = ((long)bh << 17) + b * 256L + tid;
        int dd = idx & 511;
        int t = (int)((idx >> 9) & 255);
        long so = (long)bh * TDSl + (long)(cbase + t) * DD + dd;
        wsplit(g_h + H_KH, g_h + H_KL, idx, kin[so]);
        wsplit(g_h + H_QH, g_h + H_QL, idx, q[so]);
        return;
    }
    int tx = tid & 31, ty = tid >> 5;
    if (b < 640) {
        int bb = b - 512;
        int c0 = (bb & 15) * 32, r0 = (bb >> 4) * 32;
        const float* S = v + (long)bh * TDSl + (long)cbase * DD;
#pragma unroll
        for (int j = 0; j < 4; j++) {
            int r = r0 + ty + j * 8;
            float val = S[(long)r * DD + c0 + tx];
            tile[ty + j * 8][tx] = val;
            long o = (long)bh * CHB + (long)r * DD + c0 + tx;
            wsplit(g_h + H_VH, g_h + H_VL, o, val);
        }
        __syncthreads();
#pragma unroll
        for (int j = 0; j < 4; j++) {
            int c = c0 + ty + j * 8;
            float val = tile[tx][ty + j * 8];
            long o = (long)bh * CHB + (long)c * CS + r0 + tx;
            wsplit(g_h + H_VTH, g_h + H_VTL, o, val);
        }
        return;
    }
    if (b < 768) {
        int bb = b - 640;
        int t0 = (bb & 7) * 32, d0 = (bb >> 3) * 32;
#pragma unroll
        for (int j = 0; j < 4; j++)
            tile[ty + 8 * j][tx] =
                kin[(long)bh * TDSl + (long)(cbase + t0 + ty + 8 * j) * DD + d0 + tx];
        __syncthreads();
        float l0 = lr0[(long)bh * TT + cbase + t0 + tx];
        float l2 = lr2[(long)bh * TT + cbase + t0 + tx];
#pragma unroll
        for (int j = 0; j < 4; j++) {
            long o = (long)bh * CHB + (long)(d0 + ty + 8 * j) * CS + t0 + tx;
            float kv = tile[tx][ty + 8 * j];
            wsplit(g_h + H_K0H, g_h + H_K0L, o, kv * l0);
            wsplit(g_h + H_K2H, g_h + H_K2L, o, kv * l2);
        }
        return;
    }
    {
        __shared__ float r1[256], r2[256];
        r1[tid] = mom[(long)bh * TT + cbase + tid];
        r2[tid] = mlt[(long)bh * TT + cbase + tid];
        __syncthreads();
        for (int s = 128; s > 0; s >>= 1) {
            if (tid < s) { r1[tid] += r1[tid + s]; r2[tid] += r2[tid + s]; }
            __syncthreads();
        }
        if (tid == 0) {
            g_f[F_MI + bh] = r1[0] * (1.f / CS);
            g_f[F_MLI + bh] = r2[0] * (1.f / CS);
        }
    }
}

__global__ void k_splitKQ(const float* kin, const float* q, int cbase) {
    long idx = blockIdx.x * 256L + threadIdx.x;
    int dd = idx & 511;
    int t = (int)((idx >> 9) & 255);
    int bh = (int)(idx >> 17);
    long so = (long)bh * TDSl + (long)(cbase + t) * DD + dd;
    wsplit(g_h + H_KH, g_h + H_KL, idx, kin[so]);
    wsplit(g_h + H_QH, g_h + H_QL, idx, q[so]);
}

__global__ void k_ew12T(const float* lr1, int cbase) {
    __shared__ float tile[32][33];
    int bh = blockIdx.z;
    int t0 = blockIdx.x * 32, di0 = blockIdx.y * 32;
    int tx = threadIdx.x, ty = threadIdx.y;
    float l1 = lr1[(long)bh * TT + cbase + t0 + tx];
#pragma unroll
    for (int j = 0; j < 4; j++) {
        long idx = (long)bh * CHB + (long)(di0 + ty + 8 * j) * CS + t0 + tx;
        float gba = g_f[F_GBA + idx], hbm = g_f[F_HBM + idx], dh = g_f[F_DHID + idx];
        float sg = sigf(gba), sil = gba * sg;
        wsplit(g_h + H_HLH, g_h + H_HLL, idx, sil * hbm * l1);
        wsplit(g_h + H_DBH, g_h + H_DBL, idx, dh * sil);
        float dgate = dh * hbm;
        wsplit(g_h + H_DGH, g_h + H_DGL, idx, dgate * sg * (1.f + gba * (1.f - sg)));
        float g0v = g_f[F_G0 + idx], hv = g_f[F_HH + idx];
        tile[ty + 8 * j][tx] = g0v * sigf(g0v) * hv;
    }
    __syncthreads();
#pragma unroll
    for (int j = 0; j < 4; j++) {
        long o = (long)bh * CHB + (long)(t0 + ty + 8 * j) * DI + di0 + tx;
        wsplit(g_h + H_GTH, g_h + H_GTL, o, tile[tx][ty + 8 * j]);
    }
}

__global__ void k_ewfwdT(int cbase) {
    __shared__ float tile[32][33];
    int bh = blockIdx.z;
    int t0 = blockIdx.x * 32, di0 = blockIdx.y * 32;
    int tx = threadIdx.x, ty = threadIdx.y;
#pragma unroll
    for (int j = 0; j < 4; j++) {
        long idx = (long)bh * CHB + (long)(di0 + ty + 8 * j) * CS + t0 + tx;
        float g0v = g_f[F_G0 + idx], hv = g_f[F_HH + idx];
        tile[ty + 8 * j][tx] = g0v * sigf(g0v) * hv;
    }
    __syncthreads();
#pragma unroll
    for (int j = 0; j < 4; j++) {
        long o = (long)bh * CHB + (long)(t0 + ty + 8 * j) * DI + di0 + tx;
        wsplit(g_h + H_GTH, g_h + H_GTL, o, tile[tx][ty + 8 * j]);
    }
}

// dm*rns -> X planes (pair 0) + XT planes (pair 0); rns computed in-block
__global__ void k_xsplit() {
    __shared__ float tile[32][33];
    __shared__ float rns_s;
    int m = blockIdx.z;
    int c0 = blockIdx.x * 32, r0 = blockIdx.y * 32;
    int tx = threadIdx.x, ty = threadIdx.y;
    if (tx == 0 && ty == 0) {
        float s = 0.f;
#pragma unroll
        for (int i = 0; i < 16; i++) s += g_f[F_RSP + (long)(m + 8) * 16 + i];
        rns_s = 1.f / (sqrtf(s) + 1e-7f);
    }
    __syncthreads();
    float rn = rns_s;
#pragma unroll
    for (int j = 0; j < 4; j++) {
        long i = (long)m * MSZ + (long)(r0 + ty + 8 * j) * 512 + c0 + tx;
        float v = g_f[F_DM + i] * rn;
        wsplit(g_h + H_XH, g_h + H_XL, i, v);
        tile[ty + 8 * j][tx] = v;
    }
    __syncthreads();
#pragma unroll
    for (int j = 0; j < 4; j++) {
        long o = (long)m * MSZ + (long)(c0 + ty + 8 * j) * 512 + r0 + tx;
        wsplit(g_h + H_XTH, g_h + H_XTL, o, tile[tx][ty + 8 * j]);
    }
}

__global__ void k_wupd(const bf* xh, const bf* xl) {
    int row = blockIdx.x;
    int m = row >> 9, bh = m & 7, r = row & 511;
    long mo = (long)m * MSZ + (long)r * 512;
    float ml = g_f[F_MLI + bh];
    int t = threadIdx.x;
    float vals[4];
    float ss = 0.f;
#pragma unroll
    for (int j = 0; j < 4; j++) {
        int c = t + j * 128;
        float xv = __bfloat162float(xh[mo + c]) + __bfloat162float(xl[mo + c]);
        float v = g_f[F_WM + mo + c] + xv * ml;
        g_f[F_WM + mo + c] = v;
        vals[j] = v;
        ss += v * v;
    }
    __shared__ float red[128];
    red[t] = ss; __syncthreads();
    for (int s = 64; s > 0; s >>= 1) { if (t < s) red[t] += red[t + s]; __syncthreads(); }
    float scale = g_f[F_WNORM + (long)m * 512 + r] / (sqrtf(red[0]) + 1e-5f);
#pragma unroll
    for (int j = 0; j < 4; j++) {
        int c = t + j * 128;
        float w = vals[j] * scale;
        g_f[F_WC + mo + c] = w;
        wsplit(g_h + H_WCH, g_h + H_WCL, mo + c, w);
    }
}

// ------------------------- host orchestration -------------------------------
static void setgd(GD& d, const bf* Ah, const bf* Al, long As,
                  const bf* Bh, const bf* Bl, long Bs,
                  float* C, const float* Dm, const bf* DmH, const bf* DmL, long Cs,
                  bf* OH, bf* OL, bf* OTH, bf* OTL, long Os,
                  int M, int N, int K, int csr, int csc, int flags,
                  float alpha, float beta, const float* betap) {
    d.Ah = Ah; d.Al = Al; d.Bh = Bh; d.Bl = Bl;
    d.C = C; d.Dm = Dm; d.DmH = DmH; d.DmL = DmL;
    d.OH = OH; d.OL = OL; d.OTH = OTH; d.OTL = OTL;
    d.betap = betap;
    d.As = As; d.Bs = Bs; d.Cs = Cs; d.Os = Os;
    d.M = M; d.N = N; d.K = K; d.csr = csr; d.csc = csc; d.flags = flags;
    d.alpha = alpha; d.beta = beta;
}

static void ts(const float* src, long sbs, int srows, int scols,
               bf* pH, bf* pL, long pbs, bf* tH, bf* tL, long tbs, int batch) {
    TSArgs a;
    a.src = src; a.sbs = sbs; a.srows = srows; a.scols = scols;
    a.pH = pH; a.pL = pL; a.pbs = pbs;
    a.tH = tH; a.tL = tL; a.tbs = tbs;
    k_tsplit<<<dim3(scols / 32, srows / 32, batch), dim3(32, 8)>>>(a);
}

static const float NSC[5][3] = {
    {4.0848f, -6.8946f, 2.927f},
    {3.9505f, -6.3029f, 2.6377f},
    {3.7418f, -5.5913f, 2.3037f},
    {2.8769f, -3.1427f, 1.2046f},
    {2.8366f, -3.0525f, 1.2012f}};

extern "C" void kernel_launch(void* const* d_in, const int* in_sizes, int n_in,
                              void* d_out, int out_size) {
    const float* w0  = (const float*)d_in[0];
    const float* w1  = (const float*)d_in[1];
    const float* w2  = (const float*)d_in[2];
    const float* q   = (const float*)d_in[3];
    const float* kin = (const float*)d_in[4];
    const float* v   = (const float*)d_in[5];
    const float* lr0 = (const float*)d_in[6];
    const float* lr1 = (const float*)d_in[7];
    const float* lr2 = (const float*)d_in[8];
    const float* mom = (const float*)d_in[9];
    const float* mlt = (const float*)d_in[10];
    float* out = (float*)d_out;

    static int smset = 0;
    if (!smset) {
        cudaFuncSetAttribute(tgemm, cudaFuncAttributeMaxDynamicSharedMemorySize, SMEM_TOTAL);
        smset = 1;
    }

    float* F;
    bf* H;
    cudaGetSymbolAddress((void**)&F, g_f);
    cudaGetSymbolAddress((void**)&H, g_h);

    k_init<<<NMAT * 512, 128>>>(w0, w1, w2);
    ts(F + F_WC + 8L * MSZ, MSZ, 512, 512, 0, 0, 0, H + H_W1TH, H + H_W1TL, MSZ, 8);

    for (int ci = 0; ci < NCHUNK; ci++) {
        int cb = ci * CS;

        k_pre<<<dim3(769, 1, 8), 256>>>(kin, q, v, lr0, lr2, mom, mlt, cb);

        // activation GEMMs: 5 groups of 8 -> one launch
        {
            TArgs g;
            setgd(g.gd[0], H + H_WCH, H + H_WCL, MSZ, H + H_KH, H + H_KL, CHB,
                  F + F_GBA, 0, 0, 0, CHB, 0, 0, 0, 0, 0,
                  512, 256, 512, CS, 1, 1, 1.f, 0.f, 0);
            setgd(g.gd[1], H + H_WCH + 16L * MSZ, H + H_WCL + 16L * MSZ, MSZ,
                  H + H_KH, H + H_KL, CHB, F + F_HBM, 0, 0, 0, CHB, 0, 0, 0, 0, 0,
                  512, 256, 512, CS, 1, 1, 1.f, 0.f, 0);
            setgd(g.gd[2], H + H_WCH + 16L * MSZ, H + H_WCL + 16L * MSZ, MSZ,
                  H + H_QH, H + H_QL, CHB, F + F_HH, 0, 0, 0, CHB, 0, 0, 0, 0, 0,
                  512, 256, 512, CS, 1, 1, 1.f, 0.f, 0);
            setgd(g.gd[3], H + H_WCH, H + H_WCL, MSZ, H + H_QH, H + H_QL, CHB,
                  F + F_G0, 0, 0, 0, CHB, 0, 0, 0, 0, 0,
                  512, 256, 512, CS, 1, 1, 1.f, 0.f, 0);
            setgd(g.gd[4], H + H_W1TH, H + H_W1TL, MSZ, H + H_VH, H + H_VL, CHB,
                  F + F_DHID, 0, 0, 0, CHB, 0, 0, 0, 0, 0,
                  512, 256, 512, CS, 1, 1, 1.f, 0.f, 0);
            tgemm<<<dim3(2, 4, 40), 256, SMEM_TOTAL>>>(g);
        }

        k_ew12T<<<dim3(8, 16, 8), dim3(32, 8)>>>(lr1, cb);

        // merged: out GEMM + dw GEMMs (dm = dw + dm*mi fused, sumsq partials)
        {
            TArgs g;
            setgd(g.gd[0], H + H_WCH + 8L * MSZ, H + H_WCL + 8L * MSZ, MSZ,
                  H + H_GTH, H + H_GTL, CHB,
                  out + (long)cb * DD, 0, 0, 0, TDSl, 0, 0, 0, 0, 0,
                  512, 256, 512, 1, DD, 1, 1.f, 0.f, 0);
            setgd(g.gd[1], H + H_DGH, H + H_DGL, CHB, H + H_K0H, H + H_K0L, CHB,
                  F + F_DM, F + F_DM, 0, 0, MSZ, 0, 0, 0, 0, 0,
                  512, 512, 256, 512, 1, 1 | 2 | 32, 1.f, 0.f, F + F_MI);
            setgd(g.gd[2], H + H_VTH, H + H_VTL, CHB, H + H_HLH, H + H_HLL, CHB,
                  F + F_DM + 8L * MSZ, F + F_DM + 8L * MSZ, 0, 0, MSZ, 0, 0, 0, 0, 0,
                  512, 512, 256, 512, 1, 1 | 2 | 32, 1.f, 0.f, F + F_MI);
            setgd(g.gd[3], H + H_DBH, H + H_DBL, CHB, H + H_K2H, H + H_K2L, CHB,
                  F + F_DM + 16L * MSZ, F + F_DM + 16L * MSZ, 0, 0, MSZ, 0, 0, 0, 0, 0,
                  512, 512, 256, 512, 1, 1 | 2 | 32, 1.f, 0.f, F + F_MI);
            tgemm<<<dim3(4, 4, 32), 256, SMEM_TOTAL>>>(g);
        }

        k_xsplit<<<dim3(16, 16, 24), dim3(32, 8)>>>();

        // Newton-Schulz (5 iters); X and XT planes ping-pong
        for (int it = 0; it < 5; it++) {
            float aa = NSC[it][0], bb = NSC[it][1], cc = NSC[it][2];
            long xA_h  = (it & 1) ? H_X2H : H_XH;
            long xA_l  = (it & 1) ? H_X2L : H_XL;
            long xB_h  = (it & 1) ? H_XH : H_X2H;
            long xB_l  = (it & 1) ? H_XL : H_X2L;
            long xtA_h = (it & 1) ? H_XT2H : H_XTH;
            long xtA_l = (it & 1) ? H_XT2L : H_XTL;
            long xtB_h = (it & 1) ? H_XTH : H_XT2H;
            long xtB_l = (it & 1) ? H_XTL : H_XT2L;
            // A = X @ X^T : symmetric triangle, planes only
            {
                TArgs g;
                for (int j = 0; j < 3; j++) {
                    long mb = (long)j * 8 * MSZ;
                    setgd(g.gd[j], H + xA_h + mb, H + xA_l + mb, MSZ,
                          H + xA_h + mb, H + xA_l + mb, MSZ,
                          0, 0, 0, 0, MSZ,
                          H + H_AH + mb, H + H_AL + mb, 0, 0, MSZ,
                          512, 512, 512, 512, 1, 4 | 16, 1.f, 0.f, 0);
                }
                tgemm<<<dim3(10, 1, 24), 256, SMEM_TOTAL>>>(g);
            }
            // B = b*A + c*(A@A) : symmetric triangle, beta from A planes
            {
                TArgs g;
                for (int j = 0; j < 3; j++) {
                    long mb = (long)j * 8 * MSZ;
                    setgd(g.gd[j], H + H_AH + mb, H + H_AL + mb, MSZ,
                          H + H_AH + mb, H + H_AL + mb, MSZ,
                          0, 0, H + H_AH + mb, H + H_AL + mb, MSZ,
                          H + H_BH + mb, H + H_BL + mb, 0, 0, MSZ,
                          512, 512, 512, 512, 1, 4 | 16 | 64, cc, bb, 0);
                }
                tgemm<<<dim3(10, 1, 24), 256, SMEM_TOTAL>>>(g);
            }
            // X' = a*X + B@X : Dm from X[p] planes; writes X[1-p] + XT[1-p]
            {
                TArgs g;
                for (int j = 0; j < 3; j++) {
                    long mb = (long)j * 8 * MSZ;
                    setgd(g.gd[j], H + H_BH + mb, H + H_BL + mb, MSZ,
                          H + xtA_h + mb, H + xtA_l + mb, MSZ,
                          0, 0, H + xA_h + mb, H + xA_l + mb, MSZ,
                          H + xB_h + mb, H + xB_l + mb,
                          H + xtB_h + mb, H + xtB_l + mb, MSZ,
                          512, 512, 512, 512, 1, 4 | 8 | 64, 1.f, aa, 0);
                }
                tgemm<<<dim3(4, 4, 24), 256, SMEM_TOTAL>>>(g);
            }
        }

        // after 5 iters the final X lives in pair 1 (X2 planes)
        k_wupd<<<NMAT * 512, 128>>>(H + H_X2H, H + H_X2L);
        ts(F + F_WC + 8L * MSZ, MSZ, 512, 512, 0, 0, 0, H + H_W1TH, H + H_W1TL, MSZ, 8);
    }

    // final forward-only chunk
    {
        int cb = NCHUNK * CS;
        k_splitKQ<<<(int)(CHT / 256), 256>>>(kin, q, cb);
        {
            TArgs g;
            setgd(g.gd[0], H + H_WCH + 16L * MSZ, H + H_WCL + 16L * MSZ, MSZ,
                  H + H_QH, H + H_QL, CHB, F + F_HH, 0, 0, 0, CHB, 0, 0, 0, 0, 0,
                  512, 256, 512, CS, 1, 1, 1.f, 0.f, 0);
            setgd(g.gd[1], H + H_WCH, H + H_WCL, MSZ, H + H_QH, H + H_QL, CHB,
                  F + F_G0, 0, 0, 0, CHB, 0, 0, 0, 0, 0,
                  512, 256, 512, CS, 1, 1, 1.f, 0.f, 0);
            tgemm<<<dim3(2, 4, 16), 256, SMEM_TOTAL>>>(g);
        }
        k_ewfwdT<<<dim3(8, 16, 8), dim3(32, 8)>>>(cb);
        {
            TArgs g;
            setgd(g.gd[0], H + H_WCH + 8L * MSZ, H + H_WCL + 8L * MSZ, MSZ,
                  H + H_GTH, H + H_GTL, CHB,
                  out + (long)cb * DD, 0, 0, 0, TDSl, 0, 0, 0, 0, 0,
                  512, 256, 512, 1, DD, 1, 1.f, 0.f, 0);
            tgemm<<<dim3(2, 4, 8), 256, SMEM_TOTAL>>>(g);
        }
    }
}

// round 17
// speedup vs baseline: 1.1273x; 1.0050x over previous
#include <cuda_runtime.h>
#include <cuda_bf16.h>
#include <math.h>
#include <stdint.h>

// ---------------------------------------------------------------------------
// LaCT SWIGLU fast-weight attention — mma.sync bf16-split-3 GEMM engine v3.7.
// v3.6 + vectorized plane production: bf16x2 stores (2 elems/thread) in the
// three biggest elementwise kernels (k_pre splitKQ section, k_xsplit, k_wupd),
// eliminating sub-word global stores on the hot store paths.
// ---------------------------------------------------------------------------

#define BH 8
#define TT 4096
#define DD 512
#define DI 512
#define CS 256
#define NCHUNK 15
#define NMAT 24
#define MSZ (512 * 512)
#define PLANE_B 8192
#define STAGE_B (4 * PLANE_B)
#define NSTAGE 3
#define SMEM_TOTAL (NSTAGE * STAGE_B)     // 98304 bytes

static constexpr long NM_  = (long)NMAT * MSZ;
static constexpr long W1M_ = 8L * MSZ;
static constexpr long CHB  = (long)CS * DD;
static constexpr long CHT  = (long)BH * CHB;
static constexpr long TDSl = (long)TT * DD;

// fp32 heap
static constexpr long F_WM = 0, F_WC = NM_, F_DM = 2 * NM_;
static constexpr long F_GBA = 3 * NM_, F_HBM = F_GBA + CHT, F_HH = F_HBM + CHT,
                      F_G0 = F_HH + CHT, F_DHID = F_G0 + CHT;
static constexpr long F_WNORM = F_DHID + CHT, F_MI = F_WNORM + NMAT * 512L,
                      F_MLI = F_MI + 8, F_RNS = F_MLI + 8,
                      F_RSP = F_RNS + NMAT, F_TOT = F_RSP + 512;
__device__ __align__(256) float g_f[F_TOT];

// bf16 heap
static constexpr long H_WCH = 0, H_WCL = NM_,
                      H_W1TH = 2 * NM_, H_W1TL = H_W1TH + W1M_,
                      H_XH = H_W1TL + W1M_, H_XL = H_XH + NM_,
                      H_X2H = H_XL + NM_, H_X2L = H_X2H + NM_,
                      H_XTH = H_X2L + NM_, H_XTL = H_XTH + NM_,
                      H_XT2H = H_XTL + NM_, H_XT2L = H_XT2H + NM_,
                      H_AH = H_XT2L + NM_, H_AL = H_AH + NM_,
                      H_BH = H_AL + NM_, H_BL = H_BH + NM_;
static constexpr long H_KH = H_BL + NM_, H_KL = H_KH + CHT, H_QH = H_KL + CHT,
                      H_QL = H_QH + CHT, H_VH = H_QL + CHT, H_VL = H_VH + CHT,
                      H_VTH = H_VL + CHT, H_VTL = H_VTH + CHT,
                      H_K0H = H_VTL + CHT, H_K0L = H_K0H + CHT,
                      H_K2H = H_K0L + CHT, H_K2L = H_K2H + CHT,
                      H_GTH = H_K2L + CHT, H_GTL = H_GTH + CHT,
                      H_HLH = H_GTL + CHT, H_HLL = H_HLH + CHT,
                      H_DGH = H_HLL + CHT, H_DGL = H_DGH + CHT,
                      H_DBH = H_DGL + CHT, H_DBL = H_DBH + CHT,
                      H_TOT = H_DBL + CHT;
__device__ __align__(256) __nv_bfloat16 g_h[H_TOT];

typedef __nv_bfloat16 bf;
typedef __nv_bfloat162 bf2;

// ------------------------- helpers -----------------------------------------
__device__ __forceinline__ uint32_t smem_u32(const void* p) {
    uint32_t a;
    asm("{ .reg .u64 t; cvta.to.shared.u64 t, %1; cvt.u32.u64 %0, t; }" : "=r"(a) : "l"(p));
    return a;
}
__device__ __forceinline__ void cp16(uint32_t dst, const void* src) {
    asm volatile("cp.async.cg.shared.global [%0], [%1], 16;" :: "r"(dst), "l"(src));
}
__device__ __forceinline__ void cp_commit() {
    asm volatile("cp.async.commit_group;" ::: "memory");
}
template <int N>
__device__ __forceinline__ void cp_wait() {
    asm volatile("cp.async.wait_group %0;" :: "n"(N) : "memory");
}
__device__ __forceinline__ void ldm4(uint32_t* f, uint32_t addr) {
    asm volatile("ldmatrix.sync.aligned.m8n8.x4.shared.b16 {%0,%1,%2,%3}, [%4];"
                 : "=r"(f[0]), "=r"(f[1]), "=r"(f[2]), "=r"(f[3]) : "r"(addr));
}
__device__ __forceinline__ void mma16816(float* c, const uint32_t* a, const uint32_t* b) {
    asm volatile("mma.sync.aligned.m16n8k16.row.col.f32.bf16.bf16.f32 "
                 "{%0,%1,%2,%3}, {%4,%5,%6,%7}, {%8,%9}, {%0,%1,%2,%3};"
                 : "+f"(c[0]), "+f"(c[1]), "+f"(c[2]), "+f"(c[3])
                 : "r"(a[0]), "r"(a[1]), "r"(a[2]), "r"(a[3]), "r"(b[0]), "r"(b[1]));
}
__device__ __forceinline__ void wsplit(bf* H, bf* L, long i, float v) {
    bf h = __float2bfloat16(v);
    H[i] = h;
    L[i] = __float2bfloat16(v - __bfloat162float(h));
}
// paired split: i must be even; writes H[i..i+1], L[i..i+1] as one bf2 each
__device__ __forceinline__ void wsplit2(bf* H, bf* L, long i, float v0, float v1) {
    bf h0 = __float2bfloat16(v0), h1 = __float2bfloat16(v1);
    bf2 hp; hp.x = h0; hp.y = h1;
    *reinterpret_cast<bf2*>(H + i) = hp;
    bf2 lp;
    lp.x = __float2bfloat16(v0 - __bfloat162float(h0));
    lp.y = __float2bfloat16(v1 - __bfloat162float(h1));
    *reinterpret_cast<bf2*>(L + i) = lp;
}
__device__ __forceinline__ float sigf(float x) { return 1.f / (1.f + expf(-x)); }

__device__ __forceinline__ uint32_t swzoff(int row, int kh) {
    uint32_t chunk = (uint32_t)(kh >> 3);
    return (uint32_t)row * 64u + ((chunk ^ (((uint32_t)row >> 1) & 3u)) << 4);
}

// ------------------------- GEMM kernel --------------------------------------
// flags: 1=hasC, 2=Dm fp32, 4=hasO, 8=hasOT, 16=sym, 32=redsq, 64=Dm planes
struct GD {
    const bf *Ah, *Al, *Bh, *Bl;
    float* C;
    const float* Dm;
    const bf *DmH, *DmL;
    bf *OH, *OL, *OTH, *OTL;
    const float* betap;
    long As, Bs, Cs, Os;
    int M, N, K, csr, csc, flags;
    float alpha, beta;
};
struct TArgs {
    GD gd[5];
};

__device__ __forceinline__ void ldplane(uint32_t smbase, const bf* g,
                                        int r0, int Kd, int kt, int tid) {
#pragma unroll
    for (int i = 0; i < 2; i++) {
        int idx = tid + i * 256;
        int row = idx >> 2;
        int ch = (idx & 3) << 3;
        const bf* src = g + (long)(r0 + row) * Kd + kt + ch;
        cp16(smbase + swzoff(row, ch), src);
    }
}

__global__ __launch_bounds__(256, 2) void tgemm(const __grid_constant__ TArgs g) {
    extern __shared__ bf smh[];
    uint32_t smb = smem_u32(smh);

    const int tid = threadIdx.x;
    const int lane = tid & 31;
    const int wid = tid >> 5;
    const int wm = wid >> 2;
    const int wn = wid & 3;
    const int z = blockIdx.z;
    const GD& d = g.gd[z >> 3];
    const long zb = z & 7;
    const int flags = d.flags;

    int row0, col0, bi = 0, bj = 0;
    if (flags & 16) {
        int t = blockIdx.x;
        int i = 0;
        while (t >= (i + 1) * (i + 2) / 2) i++;
        bi = i; bj = t - i * (i + 1) / 2;
        row0 = bi * 128; col0 = bj * 128;
    } else {
        row0 = blockIdx.y * 128; col0 = blockIdx.x * 128;
        if (row0 >= d.M || col0 >= d.N) return;
    }

    const bf* Ah = d.Ah + zb * d.As;
    const bf* Al = d.Al + zb * d.As;
    const bf* Bh = d.Bh + zb * d.Bs;
    const bf* Bl = d.Bl + zb * d.Bs;
    const int Kd = d.K;
    const int nslab = Kd >> 5;

    float acc[4][4][4];
#pragma unroll
    for (int i = 0; i < 4; i++)
#pragma unroll
        for (int j = 0; j < 4; j++)
#pragma unroll
            for (int r = 0; r < 4; r++) acc[i][j][r] = 0.f;

    const int lrow = lane & 15;
    const int lcol = (lane >> 4) << 3;

    {
        ldplane(smb,               Ah, row0, Kd, 0, tid);
        ldplane(smb + PLANE_B,     Al, row0, Kd, 0, tid);
        ldplane(smb + 2 * PLANE_B, Bh, col0, Kd, 0, tid);
        ldplane(smb + 3 * PLANE_B, Bl, col0, Kd, 0, tid);
        cp_commit();
        uint32_t sb = smb + STAGE_B;
        ldplane(sb,               Ah, row0, Kd, 32, tid);
        ldplane(sb + PLANE_B,     Al, row0, Kd, 32, tid);
        ldplane(sb + 2 * PLANE_B, Bh, col0, Kd, 32, tid);
        ldplane(sb + 3 * PLANE_B, Bl, col0, Kd, 32, tid);
        cp_commit();
    }

    for (int s = 0; s < nslab; s++) {
        if (s < nslab - 1) cp_wait<1>(); else cp_wait<0>();
        __syncthreads();
        if (s + 2 < nslab) {
            uint32_t sb = smb + (uint32_t)(((s + 2) % NSTAGE) * STAGE_B);
            int kt = (s + 2) << 5;
            ldplane(sb,               Ah, row0, Kd, kt, tid);
            ldplane(sb + PLANE_B,     Al, row0, Kd, kt, tid);
            ldplane(sb + 2 * PLANE_B, Bh, col0, Kd, kt, tid);
            ldplane(sb + 3 * PLANE_B, Bl, col0, Kd, kt, tid);
            cp_commit();
        }

        uint32_t sb = smb + (uint32_t)((s % NSTAGE) * STAGE_B);
#pragma unroll
        for (int k16 = 0; k16 < 2; k16++) {
            const int kh = k16 * 16 + lcol;
            uint32_t bhf[2][4], blf[2][4];
#pragma unroll
            for (int pr = 0; pr < 2; pr++) {
                int br = wn * 32 + pr * 16 + lrow;
                uint32_t off = swzoff(br, kh);
                ldm4(bhf[pr], sb + 2 * PLANE_B + off);
                ldm4(blf[pr], sb + 3 * PLANE_B + off);
            }
#pragma unroll
            for (int mt = 0; mt < 4; mt++) {
                uint32_t ahf[4], alf[4];
                int ar = wm * 64 + mt * 16 + lrow;
                uint32_t off = swzoff(ar, kh);
                ldm4(ahf, sb + off);
                ldm4(alf, sb + PLANE_B + off);
#pragma unroll
                for (int nt = 0; nt < 4; nt++) {
                    int pr = nt >> 1, hi = nt & 1;
                    uint32_t bh2[2] = {bhf[pr][hi], bhf[pr][hi + 2]};
                    mma16816(acc[mt][nt], ahf, bh2);
                }
#pragma unroll
                for (int nt = 0; nt < 4; nt++) {
                    int pr = nt >> 1, hi = nt & 1;
                    uint32_t bl2[2] = {blf[pr][hi], blf[pr][hi + 2]};
                    mma16816(acc[mt][nt], ahf, bl2);
                }
#pragma unroll
                for (int nt = 0; nt < 4; nt++) {
                    int pr = nt >> 1, hi = nt & 1;
                    uint32_t bh2[2] = {bhf[pr][hi], bhf[pr][hi + 2]};
                    mma16816(acc[mt][nt], alf, bh2);
                }
            }
        }
    }
    __syncthreads();

    // epilogue
    float* tsb = (float*)smh;
    float* C = d.C + zb * d.Cs;
    const float* Dm = d.Dm + zb * d.Cs;
    const bf* DmH = d.DmH + zb * d.Cs;
    const bf* DmL = d.DmL + zb * d.Cs;
    bf* oh = d.OH + zb * d.Os;
    bf* ol = d.OL + zb * d.Os;
    const float bcoef = d.betap ? d.betap[zb] : d.beta;
    const int gr = lane >> 2, gc = (lane & 3) * 2;
    const int domirror = (flags & 16) && (bi != bj);
    float ssq = 0.f;
#pragma unroll
    for (int mt = 0; mt < 4; mt++) {
#pragma unroll
        for (int nt = 0; nt < 4; nt++) {
#pragma unroll
            for (int rg = 0; rg < 4; rg++) {
                int rl = wm * 64 + mt * 16 + gr + ((rg >> 1) << 3);
                int cl = wn * 32 + nt * 8 + gc + (rg & 1);
                int r = row0 + rl, c = col0 + cl;
                long off = (long)r * d.csr + (long)c * d.csc;
                float val = d.alpha * acc[mt][nt][rg];
                if (flags & 2) val += bcoef * Dm[off];
                if (flags & 64)
                    val += bcoef * (__bfloat162float(DmH[off]) + __bfloat162float(DmL[off]));
                if (flags & 1) C[off] = val;
                if (flags & 32) ssq += val * val;
                bf vh = __float2bfloat16(val);
                bf vl = __float2bfloat16(val - __bfloat162float(vh));
                if (flags & 4) { oh[off] = vh; ol[off] = vl; }
                if (domirror) {
                    long offm = (long)c * d.csr + (long)r * d.csc;
                    if (flags & 1) C[offm] = val;
                    if (flags & 4) { oh[offm] = vh; ol[offm] = vl; }
                }
                if (flags & 8) tsb[rl * 129 + cl] = val;
            }
        }
    }
    if (flags & 32) {
#pragma unroll
        for (int o = 16; o > 0; o >>= 1) ssq += __shfl_xor_sync(0xffffffffu, ssq, o);
        float* rs = (float*)smh;
        if (lane == 0) rs[wid] = ssq;
        __syncthreads();
        if (tid == 0) {
            float tot = 0.f;
#pragma unroll
            for (int w = 0; w < 8; w++) tot += rs[w];
            g_f[F_RSP + (long)z * 16 + blockIdx.y * 4 + blockIdx.x] = tot;
        }
    }
    if (flags & 8) {
        __syncthreads();
        bf* oth = d.OTH + zb * d.Os;
        bf* otl = d.OTL + zb * d.Os;
#pragma unroll 4
        for (int i = 0; i < 64; i++) {
            int idx = tid + i * 256;
            int cl = idx >> 7;
            int rl = idx & 127;
            float v = tsb[rl * 129 + cl];
            long off = (long)(col0 + cl) * 512 + row0 + rl;
            bf h = __float2bfloat16(v);
            oth[off] = h;
            otl[off] = __float2bfloat16(v - __bfloat162float(h));
        }
    }
}

// ------------------------- transpose/split (fp32 src -> planes) -------------
struct TSArgs {
    const float* src; long sbs; int srows, scols;
    bf *pH, *pL; long pbs;
    bf *tH, *tL; long tbs;
};
__global__ void k_tsplit(const __grid_constant__ TSArgs a) {
    __shared__ float tile[32][33];
    int z = blockIdx.z;
    const float* S = a.src + (long)z * a.sbs;
    int c0 = blockIdx.x * 32, r0 = blockIdx.y * 32;
    int tx = threadIdx.x, ty = threadIdx.y;
#pragma unroll
    for (int j = 0; j < 4; j++) {
        int r = r0 + ty + j * 8;
        float v = S[(long)r * a.scols + c0 + tx];
        tile[ty + j * 8][tx] = v;
        if (a.pH) {
            long o = (long)z * a.pbs + (long)r * a.scols + c0 + tx;
            wsplit(a.pH, a.pL, o, v);
        }
    }
    __syncthreads();
    if (a.tH) {
#pragma unroll
        for (int j = 0; j < 4; j++) {
            int c = c0 + ty + j * 8;
            float v = tile[tx][ty + j * 8];
            long o = (long)z * a.tbs + (long)c * a.srows + r0 + tx;
            wsplit(a.tH, a.tL, o, v);
        }
    }
}

// ------------------------- elementwise/fused kernels ------------------------
__global__ void k_init(const float* w0, const float* w1, const float* w2) {
    int row = blockIdx.x;
    int m = row >> 9, w = m >> 3, bh = m & 7, r = row & 511;
    const float* src = (w == 0 ? w0 : (w == 1 ? w1 : w2)) + (long)bh * MSZ + (long)r * 512;
    long mo = (long)m * MSZ + (long)r * 512;
    int t = threadIdx.x;
    float ss = 0.f;
#pragma unroll
    for (int j = 0; j < 4; j++) {
        int c = t + j * 128;
        float v = src[c];
        g_f[F_WM + mo + c] = v;
        g_f[F_WC + mo + c] = v;
        g_f[F_DM + mo + c] = 0.f;
        wsplit(g_h + H_WCH, g_h + H_WCL, mo + c, v);
        ss += v * v;
    }
    __shared__ float red[128];
    red[t] = ss; __syncthreads();
    for (int s = 64; s > 0; s >>= 1) { if (t < s) red[t] += red[t + s]; __syncthreads(); }
    if (t == 0) g_f[F_WNORM + (long)m * 512 + r] = sqrtf(red[0]);
}

// one launch: splitKQ (256 blk/bh, 2 elems/thr) + V split/T (128) + k*lr (128) + scalars (1)
__global__ void k_pre(const float* kin, const float* q, const float* v,
                      const float* lr0, const float* lr2,
                      const float* mom, const float* mlt, int cbase) {
    __shared__ float tile[32][33];
    int bh = blockIdx.z;
    int b = blockIdx.x;
    int tid = threadIdx.x;
    if (b < 256) {
        long base = ((long)bh << 17) + (long)(b * 256 + tid) * 2;
        int dd = (int)(base & 511);
        int t = (int)((base >> 9) & 255);
        long so = (long)bh * TDSl + (long)(cbase + t) * DD + dd;
        float2 kv = *reinterpret_cast<const float2*>(kin + so);
        float2 qv = *reinterpret_cast<const float2*>(q + so);
        wsplit2(g_h + H_KH, g_h + H_KL, base, kv.x, kv.y);
        wsplit2(g_h + H_QH, g_h + H_QL, base, qv.x, qv.y);
        return;
    }
    int tx = tid & 31, ty = tid >> 5;
    if (b < 384) {
        int bb = b - 256;
        int c0 = (bb & 15) * 32, r0 = (bb >> 4) * 32;
        const float* S = v + (long)bh * TDSl + (long)cbase * DD;
#pragma unroll
        for (int j = 0; j < 4; j++) {
            int r = r0 + ty + j * 8;
            float val = S[(long)r * DD + c0 + tx];
            tile[ty + j * 8][tx] = val;
            long o = (long)bh * CHB + (long)r * DD + c0 + tx;
            wsplit(g_h + H_VH, g_h + H_VL, o, val);
        }
        __syncthreads();
#pragma unroll
        for (int j = 0; j < 4; j++) {
            int c = c0 + ty + j * 8;
            float val = tile[tx][ty + j * 8];
            long o = (long)bh * CHB + (long)c * CS + r0 + tx;
            wsplit(g_h + H_VTH, g_h + H_VTL, o, val);
        }
        return;
    }
    if (b < 512) {
        int bb = b - 384;
        int t0 = (bb & 7) * 32, d0 = (bb >> 3) * 32;
#pragma unroll
        for (int j = 0; j < 4; j++)
            tile[ty + 8 * j][tx] =
                kin[(long)bh * TDSl + (long)(cbase + t0 + ty + 8 * j) * DD + d0 + tx];
        __syncthreads();
        float l0 = lr0[(long)bh * TT + cbase + t0 + tx];
        float l2 = lr2[(long)bh * TT + cbase + t0 + tx];
#pragma unroll
        for (int j = 0; j < 4; j++) {
            long o = (long)bh * CHB + (long)(d0 + ty + 8 * j) * CS + t0 + tx;
            float kv = tile[tx][ty + 8 * j];
            wsplit(g_h + H_K0H, g_h + H_K0L, o, kv * l0);
            wsplit(g_h + H_K2H, g_h + H_K2L, o, kv * l2);
        }
        return;
    }
    {
        __shared__ float r1[256], r2[256];
        r1[tid] = mom[(long)bh * TT + cbase + tid];
        r2[tid] = mlt[(long)bh * TT + cbase + tid];
        __syncthreads();
        for (int s = 128; s > 0; s >>= 1) {
            if (tid < s) { r1[tid] += r1[tid + s]; r2[tid] += r2[tid + s]; }
            __syncthreads();
        }
        if (tid == 0) {
            g_f[F_MI + bh] = r1[0] * (1.f / CS);
            g_f[F_MLI + bh] = r2[0] * (1.f / CS);
        }
    }
}

__global__ void k_splitKQ(const float* kin, const float* q, int cbase) {
    long idx = blockIdx.x * 256L + threadIdx.x;
    int dd = idx & 511;
    int t = (int)((idx >> 9) & 255);
    int bh = (int)(idx >> 17);
    long so = (long)bh * TDSl + (long)(cbase + t) * DD + dd;
    wsplit(g_h + H_KH, g_h + H_KL, idx, kin[so]);
    wsplit(g_h + H_QH, g_h + H_QL, idx, q[so]);
}

__global__ void k_ew12T(const float* lr1, int cbase) {
    __shared__ float tile[32][33];
    int bh = blockIdx.z;
    int t0 = blockIdx.x * 32, di0 = blockIdx.y * 32;
    int tx = threadIdx.x, ty = threadIdx.y;
    float l1 = lr1[(long)bh * TT + cbase + t0 + tx];
#pragma unroll
    for (int j = 0; j < 4; j++) {
        long idx = (long)bh * CHB + (long)(di0 + ty + 8 * j) * CS + t0 + tx;
        float gba = g_f[F_GBA + idx], hbm = g_f[F_HBM + idx], dh = g_f[F_DHID + idx];
        float sg = sigf(gba), sil = gba * sg;
        wsplit(g_h + H_HLH, g_h + H_HLL, idx, sil * hbm * l1);
        wsplit(g_h + H_DBH, g_h + H_DBL, idx, dh * sil);
        float dgate = dh * hbm;
        wsplit(g_h + H_DGH, g_h + H_DGL, idx, dgate * sg * (1.f + gba * (1.f - sg)));
        float g0v = g_f[F_G0 + idx], hv = g_f[F_HH + idx];
        tile[ty + 8 * j][tx] = g0v * sigf(g0v) * hv;
    }
    __syncthreads();
#pragma unroll
    for (int j = 0; j < 4; j++) {
        long o = (long)bh * CHB + (long)(t0 + ty + 8 * j) * DI + di0 + tx;
        wsplit(g_h + H_GTH, g_h + H_GTL, o, tile[tx][ty + 8 * j]);
    }
}

__global__ void k_ewfwdT(int cbase) {
    __shared__ float tile[32][33];
    int bh = blockIdx.z;
    int t0 = blockIdx.x * 32, di0 = blockIdx.y * 32;
    int tx = threadIdx.x, ty = threadIdx.y;
#pragma unroll
    for (int j = 0; j < 4; j++) {
        long idx = (long)bh * CHB + (long)(di0 + ty + 8 * j) * CS + t0 + tx;
        float g0v = g_f[F_G0 + idx], hv = g_f[F_HH + idx];
        tile[ty + 8 * j][tx] = g0v * sigf(g0v) * hv;
    }
    __syncthreads();
#pragma unroll
    for (int j = 0; j < 4; j++) {
        long o = (long)bh * CHB + (long)(t0 + ty + 8 * j) * DI + di0 + tx;
        wsplit(g_h + H_GTH, g_h + H_GTL, o, tile[tx][ty + 8 * j]);
    }
}

// dm*rns -> X planes + XT planes (pair 0); rns in-block; bf2 vectorized stores
// grid (8, 16, 24), block 256: tile 32 rows x 64 cols
__global__ void k_xsplit() {
    __shared__ float tile[32][65];
    __shared__ float rns_s;
    int m = blockIdx.z;
    int c0 = blockIdx.x * 64, r0 = blockIdx.y * 32;
    int tid = threadIdx.x;
    int tx = tid & 31, ty = tid >> 5;
    if (tid == 0) {
        float s = 0.f;
#pragma unroll
        for (int i = 0; i < 16; i++) s += g_f[F_RSP + (long)(m + 8) * 16 + i];
        rns_s = 1.f / (sqrtf(s) + 1e-7f);
    }
    __syncthreads();
    float rn = rns_s;
#pragma unroll
    for (int j = 0; j < 4; j++) {
        int r = r0 + ty + 8 * j;
        long i = (long)m * MSZ + (long)r * 512 + c0 + 2 * tx;
        float2 dv = *reinterpret_cast<const float2*>(g_f + F_DM + i);
        float v0 = dv.x * rn, v1 = dv.y * rn;
        wsplit2(g_h + H_XH, g_h + H_XL, i, v0, v1);
        tile[ty + 8 * j][2 * tx] = v0;
        tile[ty + 8 * j][2 * tx + 1] = v1;
    }
    __syncthreads();
#pragma unroll
    for (int j = 0; j < 4; j++) {
        int id = tid + 256 * j;          // 0..1023
        int ocol = id >> 4;              // 0..63
        int rp = id & 15;                // row pair 0..15
        float v0 = tile[2 * rp][ocol];
        float v1 = tile[2 * rp + 1][ocol];
        long o = (long)m * MSZ + (long)(c0 + ocol) * 512 + r0 + 2 * rp;
        wsplit2(g_h + H_XTH, g_h + H_XTL, o, v0, v1);
    }
}

// weight update: 4 consecutive cols/thread, float4 + bf2 traffic
__global__ void k_wupd(const bf* xh, const bf* xl) {
    int row = blockIdx.x;
    int m = row >> 9, bh = m & 7, r = row & 511;
    long mo = (long)m * MSZ + (long)r * 512;
    float ml = g_f[F_MLI + bh];
    int t = threadIdx.x;
    int c = t * 4;
    float4 wm = *reinterpret_cast<const float4*>(g_f + F_WM + mo + c);
    bf2 xh0 = *reinterpret_cast<const bf2*>(xh + mo + c);
    bf2 xh1 = *reinterpret_cast<const bf2*>(xh + mo + c + 2);
    bf2 xl0 = *reinterpret_cast<const bf2*>(xl + mo + c);
    bf2 xl1 = *reinterpret_cast<const bf2*>(xl + mo + c + 2);
    float v0 = wm.x + (__bfloat162float(xh0.x) + __bfloat162float(xl0.x)) * ml;
    float v1 = wm.y + (__bfloat162float(xh0.y) + __bfloat162float(xl0.y)) * ml;
    float v2 = wm.z + (__bfloat162float(xh1.x) + __bfloat162float(xl1.x)) * ml;
    float v3 = wm.w + (__bfloat162float(xh1.y) + __bfloat162float(xl1.y)) * ml;
    float4 wv = make_float4(v0, v1, v2, v3);
    *reinterpret_cast<float4*>(g_f + F_WM + mo + c) = wv;
    float ss = v0 * v0 + v1 * v1 + v2 * v2 + v3 * v3;
    __shared__ float red[128];
    red[t] = ss; __syncthreads();
    for (int s = 64; s > 0; s >>= 1) { if (t < s) red[t] += red[t + s]; __syncthreads(); }
    float scale = g_f[F_WNORM + (long)m * 512 + r] / (sqrtf(red[0]) + 1e-5f);
    float w0 = v0 * scale, w1 = v1 * scale, w2 = v2 * scale, w3 = v3 * scale;
    *reinterpret_cast<float4*>(g_f + F_WC + mo + c) = make_float4(w0, w1, w2, w3);
    wsplit2(g_h + H_WCH, g_h + H_WCL, mo + c, w0, w1);
    wsplit2(g_h + H_WCH, g_h + H_WCL, mo + c + 2, w2, w3);
}

// ------------------------- host orchestration -------------------------------
static void setgd(GD& d, const bf* Ah, const bf* Al, long As,
                  const bf* Bh, const bf* Bl, long Bs,
                  float* C, const float* Dm, const bf* DmH, const bf* DmL, long Cs,
                  bf* OH, bf* OL, bf* OTH, bf* OTL, long Os,
                  int M, int N, int K, int csr, int csc, int flags,
                  float alpha, float beta, const float* betap) {
    d.Ah = Ah; d.Al = Al; d.Bh = Bh; d.Bl = Bl;
    d.C = C; d.Dm = Dm; d.DmH = DmH; d.DmL = DmL;
    d.OH = OH; d.OL = OL; d.OTH = OTH; d.OTL = OTL;
    d.betap = betap;
    d.As = As; d.Bs = Bs; d.Cs = Cs; d.Os = Os;
    d.M = M; d.N = N; d.K = K; d.csr = csr; d.csc = csc; d.flags = flags;
    d.alpha = alpha; d.beta = beta;
}

static void ts(const float* src, long sbs, int srows, int scols,
               bf* pH, bf* pL, long pbs, bf* tH, bf* tL, long tbs, int batch) {
    TSArgs a;
    a.src = src; a.sbs = sbs; a.srows = srows; a.scols = scols;
    a.pH = pH; a.pL = pL; a.pbs = pbs;
    a.tH = tH; a.tL = tL; a.tbs = tbs;
    k_tsplit<<<dim3(scols / 32, srows / 32, batch), dim3(32, 8)>>>(a);
}

static const float NSC[5][3] = {
    {4.0848f, -6.8946f, 2.927f},
    {3.9505f, -6.3029f, 2.6377f},
    {3.7418f, -5.5913f, 2.3037f},
    {2.8769f, -3.1427f, 1.2046f},
    {2.8366f, -3.0525f, 1.2012f}};

extern "C" void kernel_launch(void* const* d_in, const int* in_sizes, int n_in,
                              void* d_out, int out_size) {
    const float* w0  = (const float*)d_in[0];
    const float* w1  = (const float*)d_in[1];
    const float* w2  = (const float*)d_in[2];
    const float* q   = (const float*)d_in[3];
    const float* kin = (const float*)d_in[4];
    const float* v   = (const float*)d_in[5];
    const float* lr0 = (const float*)d_in[6];
    const float* lr1 = (const float*)d_in[7];
    const float* lr2 = (const float*)d_in[8];
    const float* mom = (const float*)d_in[9];
    const float* mlt = (const float*)d_in[10];
    float* out = (float*)d_out;

    static int smset = 0;
    if (!smset) {
        cudaFuncSetAttribute(tgemm, cudaFuncAttributeMaxDynamicSharedMemorySize, SMEM_TOTAL);
        smset = 1;
    }

    float* F;
    bf* H;
    cudaGetSymbolAddress((void**)&F, g_f);
    cudaGetSymbolAddress((void**)&H, g_h);

    k_init<<<NMAT * 512, 128>>>(w0, w1, w2);
    ts(F + F_WC + 8L * MSZ, MSZ, 512, 512, 0, 0, 0, H + H_W1TH, H + H_W1TL, MSZ, 8);

    for (int ci = 0; ci < NCHUNK; ci++) {
        int cb = ci * CS;

        k_pre<<<dim3(513, 1, 8), 256>>>(kin, q, v, lr0, lr2, mom, mlt, cb);

        // activation GEMMs: 5 groups of 8 -> one launch
        {
            TArgs g;
            setgd(g.gd[0], H + H_WCH, H + H_WCL, MSZ, H + H_KH, H + H_KL, CHB,
                  F + F_GBA, 0, 0, 0, CHB, 0, 0, 0, 0, 0,
                  512, 256, 512, CS, 1, 1, 1.f, 0.f, 0);
            setgd(g.gd[1], H + H_WCH + 16L * MSZ, H + H_WCL + 16L * MSZ, MSZ,
                  H + H_KH, H + H_KL, CHB, F + F_HBM, 0, 0, 0, CHB, 0, 0, 0, 0, 0,
                  512, 256, 512, CS, 1, 1, 1.f, 0.f, 0);
            setgd(g.gd[2], H + H_WCH + 16L * MSZ, H + H_WCL + 16L * MSZ, MSZ,
                  H + H_QH, H + H_QL, CHB, F + F_HH, 0, 0, 0, CHB, 0, 0, 0, 0, 0,
                  512, 256, 512, CS, 1, 1, 1.f, 0.f, 0);
            setgd(g.gd[3], H + H_WCH, H + H_WCL, MSZ, H + H_QH, H + H_QL, CHB,
                  F + F_G0, 0, 0, 0, CHB, 0, 0, 0, 0, 0,
                  512, 256, 512, CS, 1, 1, 1.f, 0.f, 0);
            setgd(g.gd[4], H + H_W1TH, H + H_W1TL, MSZ, H + H_VH, H + H_VL, CHB,
                  F + F_DHID, 0, 0, 0, CHB, 0, 0, 0, 0, 0,
                  512, 256, 512, CS, 1, 1, 1.f, 0.f, 0);
            tgemm<<<dim3(2, 4, 40), 256, SMEM_TOTAL>>>(g);
        }

        k_ew12T<<<dim3(8, 16, 8), dim3(32, 8)>>>(lr1, cb);

        // merged: out GEMM + dw GEMMs (dm = dw + dm*mi fused, sumsq partials)
        {
            TArgs g;
            setgd(g.gd[0], H + H_WCH + 8L * MSZ, H + H_WCL + 8L * MSZ, MSZ,
                  H + H_GTH, H + H_GTL, CHB,
                  out + (long)cb * DD, 0, 0, 0, TDSl, 0, 0, 0, 0, 0,
                  512, 256, 512, 1, DD, 1, 1.f, 0.f, 0);
            setgd(g.gd[1], H + H_DGH, H + H_DGL, CHB, H + H_K0H, H + H_K0L, CHB,
                  F + F_DM, F + F_DM, 0, 0, MSZ, 0, 0, 0, 0, 0,
                  512, 512, 256, 512, 1, 1 | 2 | 32, 1.f, 0.f, F + F_MI);
            setgd(g.gd[2], H + H_VTH, H + H_VTL, CHB, H + H_HLH, H + H_HLL, CHB,
                  F + F_DM + 8L * MSZ, F + F_DM + 8L * MSZ, 0, 0, MSZ, 0, 0, 0, 0, 0,
                  512, 512, 256, 512, 1, 1 | 2 | 32, 1.f, 0.f, F + F_MI);
            setgd(g.gd[3], H + H_DBH, H + H_DBL, CHB, H + H_K2H, H + H_K2L, CHB,
                  F + F_DM + 16L * MSZ, F + F_DM + 16L * MSZ, 0, 0, MSZ, 0, 0, 0, 0, 0,
                  512, 512, 256, 512, 1, 1 | 2 | 32, 1.f, 0.f, F + F_MI);
            tgemm<<<dim3(4, 4, 32), 256, SMEM_TOTAL>>>(g);
        }

        k_xsplit<<<dim3(8, 16, 24), 256>>>();

        // Newton-Schulz (5 iters); X and XT planes ping-pong
        for (int it = 0; it < 5; it++) {
            float aa = NSC[it][0], bb = NSC[it][1], cc = NSC[it][2];
            long xA_h  = (it & 1) ? H_X2H : H_XH;
            long xA_l  = (it & 1) ? H_X2L : H_XL;
            long xB_h  = (it & 1) ? H_XH : H_X2H;
            long xB_l  = (it & 1) ? H_XL : H_X2L;
            long xtA_h = (it & 1) ? H_XT2H : H_XTH;
            long xtA_l = (it & 1) ? H_XT2L : H_XTL;
            long xtB_h = (it & 1) ? H_XTH : H_XT2H;
            long xtB_l = (it & 1) ? H_XTL : H_XT2L;
            {
                TArgs g;
                for (int j = 0; j < 3; j++) {
                    long mb = (long)j * 8 * MSZ;
                    setgd(g.gd[j], H + xA_h + mb, H + xA_l + mb, MSZ,
                          H + xA_h + mb, H + xA_l + mb, MSZ,
                          0, 0, 0, 0, MSZ,
                          H + H_AH + mb, H + H_AL + mb, 0, 0, MSZ,
                          512, 512, 512, 512, 1, 4 | 16, 1.f, 0.f, 0);
                }
                tgemm<<<dim3(10, 1, 24), 256, SMEM_TOTAL>>>(g);
            }
            {
                TArgs g;
                for (int j = 0; j < 3; j++) {
                    long mb = (long)j * 8 * MSZ;
                    setgd(g.gd[j], H + H_AH + mb, H + H_AL + mb, MSZ,
                          H + H_AH + mb, H + H_AL + mb, MSZ,
                          0, 0, H + H_AH + mb, H + H_AL + mb, MSZ,
                          H + H_BH + mb, H + H_BL + mb, 0, 0, MSZ,
                          512, 512, 512, 512, 1, 4 | 16 | 64, cc, bb, 0);
                }
                tgemm<<<dim3(10, 1, 24), 256, SMEM_TOTAL>>>(g);
            }
            {
                TArgs g;
                for (int j = 0; j < 3; j++) {
                    long mb = (long)j * 8 * MSZ;
                    setgd(g.gd[j], H + H_BH + mb, H + H_BL + mb, MSZ,
                          H + xtA_h + mb, H + xtA_l + mb, MSZ,
                          0, 0, H + xA_h + mb, H + xA_l + mb, MSZ,
                          H + xB_h + mb, H + xB_l + mb,
                          H + xtB_h + mb, H + xtB_l + mb, MSZ,
                          512, 512, 512, 512, 1, 4 | 8 | 64, 1.f, aa, 0);
                }
                tgemm<<<dim3(4, 4, 24), 256, SMEM_TOTAL>>>(g);
            }
        }

        k_wupd<<<NMAT * 512, 128>>>(H + H_X2H, H + H_X2L);
        ts(F + F_WC + 8L * MSZ, MSZ, 512, 512, 0, 0, 0, H + H_W1TH, H + H_W1TL, MSZ, 8);
    }

    // final forward-only chunk
    {
        int cb = NCHUNK * CS;
        k_splitKQ<<<(int)(CHT / 256), 256>>>(kin, q, cb);
        {
            TArgs g;
            setgd(g.gd[0], H + H_WCH + 16L * MSZ, H + H_WCL + 16L * MSZ, MSZ,
                  H + H_QH, H + H_QL, CHB, F + F_HH, 0, 0, 0, CHB, 0, 0, 0, 0, 0,
                  512, 256, 512, CS, 1, 1, 1.f, 0.f, 0);
            setgd(g.gd[1], H + H_WCH, H + H_WCL, MSZ, H + H_QH, H + H_QL, CHB,
                  F + F_G0, 0, 0, 0, CHB, 0, 0, 0, 0, 0,
                  512, 256, 512, CS, 1, 1, 1.f, 0.f, 0);
            tgemm<<<dim3(2, 4, 16), 256, SMEM_TOTAL>>>(g);
        }
        k_ewfwdT<<<dim3(8, 16, 8), dim3(32, 8)>>>(cb);
        {
            TArgs g;
            setgd(g.gd[0], H + H_WCH + 8L * MSZ, H + H_WCL + 8L * MSZ, MSZ,
                  H + H_GTH, H + H_GTL, CHB,
                  out + (long)cb * DD, 0, 0, 0, TDSl, 0, 0, 0, 0, 0,
                  512, 256, 512, 1, DD, 1, 1.f, 0.f, 0);
            tgemm<<<dim3(2, 4, 8), 256, SMEM_TOTAL>>>(g);
        }
    }
}